// round 6
// baseline (speedup 1.0000x reference)
#include <cuda_runtime.h>
#include <cuda_bf16.h>
#include <math.h>
#include <stdint.h>

// Problem constants
#define BATCH 2
#define SEQ 2048
#define DMODEL 1024
#define NHEADS 16
#define HDIM 64
#define MROWS (BATCH*SEQ)              // 4096
#define OUTN  (BATCH*SEQ*DMODEL)       // 4194304
#define KVN   (BATCH*NHEADS*SEQ*HDIM)  // 4194304
#define WN    (DMODEL*DMODEL)          // 1048576

// ---------------- scratch (device globals; no allocations allowed) ----------
__device__ float g_kfb[KVN];
__device__ float g_vfb[KVN];
__device__ __nv_bfloat16 g_xh[OUTN];
__device__ __nv_bfloat16 g_xl[OUTN];
__device__ __nv_bfloat16 g_wqh[WN], g_wql[WN];
__device__ __nv_bfloat16 g_wkh[WN], g_wkl[WN];
__device__ __nv_bfloat16 g_wvh[WN], g_wvl[WN];
__device__ __nv_bfloat16 g_woh[WN], g_wol[WN];
__device__ __nv_bfloat16 g_qh[KVN], g_ql[KVN];
__device__ __nv_bfloat16 g_kh[KVN], g_kl[KVN];
__device__ __nv_bfloat16 g_vh[KVN], g_vl[KVN];

// ====================== helpers ==============================================
__device__ __forceinline__ uint32_t smem_to_u32(const void* p) {
    uint32_t a;
    asm("{ .reg .u64 t; cvta.to.shared.u64 t, %1; cvt.u32.u64 %0, t; }"
        : "=r"(a) : "l"(p));
    return a;
}

__device__ __forceinline__ void cp16(uint32_t saddr, const void* g) {
    asm volatile("cp.async.cg.shared.global [%0], [%1], 16;"
                 :: "r"(saddr), "l"(g) : "memory");
}

#define LDSM4(r0, r1, r2, r3, addr) \
    asm volatile("ldmatrix.sync.aligned.m8n8.x4.shared.b16 {%0,%1,%2,%3}, [%4];" \
                 : "=r"(r0), "=r"(r1), "=r"(r2), "=r"(r3) : "r"(addr))

#define LDSM4T(r0, r1, r2, r3, addr) \
    asm volatile("ldmatrix.sync.aligned.m8n8.x4.trans.shared.b16 {%0,%1,%2,%3}, [%4];" \
                 : "=r"(r0), "=r"(r1), "=r"(r2), "=r"(r3) : "r"(addr))

#define MMA16816(d, a0, a1, a2, a3, b0, b1) \
    asm volatile("mma.sync.aligned.m16n8k16.row.col.f32.bf16.bf16.f32 " \
                 "{%0,%1,%2,%3}, {%4,%5,%6,%7}, {%8,%9}, {%0,%1,%2,%3};" \
                 : "+f"((d)[0]), "+f"((d)[1]), "+f"((d)[2]), "+f"((d)[3]) \
                 : "r"(a0), "r"(a1), "r"(a2), "r"(a3), "r"(b0), "r"(b1))

__device__ __forceinline__ uint32_t pack_bf16(float a, float b) {
    __nv_bfloat162 v = __halves2bfloat162(__float2bfloat16(a), __float2bfloat16(b));
    return *(uint32_t*)&v;
}

__device__ __forceinline__ void store_split2(__nv_bfloat16* H, __nv_bfloat16* L,
                                             size_t idx, float a, float b) {
    __nv_bfloat16 ha = __float2bfloat16(a), hb = __float2bfloat16(b);
    float ra = a - __bfloat162float(ha), rb = b - __bfloat162float(hb);
    *(__nv_bfloat162*)(H + idx) = __halves2bfloat162(ha, hb);
    *(__nv_bfloat162*)(L + idx) =
        __halves2bfloat162(__float2bfloat16(ra), __float2bfloat16(rb));
}

struct RopeTab { float hi[32]; float lo[32]; };

// ====================== bf16 split conversion ================================
__global__ void split_kernel(const float4* __restrict__ src,
                             __nv_bfloat162* __restrict__ hi,
                             __nv_bfloat162* __restrict__ lo, int n4)
{
    int i = blockIdx.x * blockDim.x + threadIdx.x;
    if (i >= n4) return;
    float4 v = src[i];
    __nv_bfloat16 h0 = __float2bfloat16(v.x);
    __nv_bfloat16 h1 = __float2bfloat16(v.y);
    __nv_bfloat16 h2 = __float2bfloat16(v.z);
    __nv_bfloat16 h3 = __float2bfloat16(v.w);
    float r0 = v.x - __bfloat162float(h0);
    float r1 = v.y - __bfloat162float(h1);
    float r2 = v.z - __bfloat162float(h2);
    float r3 = v.w - __bfloat162float(h3);
    hi[2*i]   = __halves2bfloat162(h0, h1);
    hi[2*i+1] = __halves2bfloat162(h2, h3);
    lo[2*i]   = __halves2bfloat162(__float2bfloat16(r0), __float2bfloat16(r1));
    lo[2*i+1] = __halves2bfloat162(__float2bfloat16(r2), __float2bfloat16(r3));
}

struct Ptrs4 {
    const float4* s[4];
    __nv_bfloat162* h[4];
    __nv_bfloat162* l[4];
};

__global__ void wsplit(Ptrs4 p, int n4)
{
    int i = blockIdx.x * blockDim.x + threadIdx.x;
    int w = blockIdx.y;
    if (i >= n4) return;
    float4 v = p.s[w][i];
    __nv_bfloat16 h0 = __float2bfloat16(v.x);
    __nv_bfloat16 h1 = __float2bfloat16(v.y);
    __nv_bfloat16 h2 = __float2bfloat16(v.z);
    __nv_bfloat16 h3 = __float2bfloat16(v.w);
    float r0 = v.x - __bfloat162float(h0);
    float r1 = v.y - __bfloat162float(h1);
    float r2 = v.z - __bfloat162float(h2);
    float r3 = v.w - __bfloat162float(h3);
    p.h[w][2*i]   = __halves2bfloat162(h0, h1);
    p.h[w][2*i+1] = __halves2bfloat162(h2, h3);
    p.l[w][2*i]   = __halves2bfloat162(__float2bfloat16(r0), __float2bfloat16(r1));
    p.l[w][2*i+1] = __halves2bfloat162(__float2bfloat16(r2), __float2bfloat16(r3));
}

// ====================== mma.sync split-bf16 GEMM core =========================
#define TB 16384
#define STAGE (4*TB)
#define GEMM_SMEM (2*STAGE)
#define NCK 16

__device__ __forceinline__ void stage_load(uint32_t sb,
    const uint4* __restrict__ Ah, const uint4* __restrict__ Al,
    const uint4* __restrict__ Bh, const uint4* __restrict__ Bl,
    int m0, int n0, int c, int tid)
{
    const int q = tid & 7;
    const int r0 = tid >> 3;
#pragma unroll
    for (int it = 0; it < 4; it++) {
        int row = r0 + it * 32;
        uint32_t off = row * 128 + q * 16;
        off ^= (off >> 3) & 0x70;
        size_t ga = (size_t)(m0 + row) * 128 + c * 8 + q;
        size_t gb = (size_t)(n0 + row) * 128 + c * 8 + q;
        cp16(sb + off,          Ah + ga);
        cp16(sb + TB + off,     Al + ga);
        cp16(sb + 2*TB + off,   Bh + gb);
        cp16(sb + 3*TB + off,   Bl + gb);
    }
}

__device__ __forceinline__ void gemm_mainloop(uint32_t sbase,
    const uint4* A4h, const uint4* A4l, const uint4* B4h, const uint4* B4l,
    int m0, int n0, int tid, int wm, int wn,
    int arow, int acolb, int brow, int bcolb, float acc[4][4][4])
{
#pragma unroll
    for (int i = 0; i < 4; i++)
#pragma unroll
        for (int j = 0; j < 4; j++)
#pragma unroll
            for (int r = 0; r < 4; r++) acc[i][j][r] = 0.f;

    stage_load(sbase, A4h, A4l, B4h, B4l, m0, n0, 0, tid);
    asm volatile("cp.async.commit_group;" ::: "memory");

    for (int c = 0; c < NCK; c++) {
        __syncthreads();
        if (c + 1 < NCK) {
            stage_load(sbase + (uint32_t)((c + 1) & 1) * STAGE,
                       A4h, A4l, B4h, B4l, m0, n0, c + 1, tid);
            asm volatile("cp.async.commit_group;" ::: "memory");
            asm volatile("cp.async.wait_group 1;" ::: "memory");
        } else {
            asm volatile("cp.async.wait_group 0;" ::: "memory");
        }
        __syncthreads();

        const uint32_t sb  = sbase + (uint32_t)(c & 1) * STAGE;
        const uint32_t sAh = sb;
        const uint32_t sAl = sb + TB;
        const uint32_t sBh = sb + 2*TB;
        const uint32_t sBl = sb + 3*TB;

#pragma unroll
        for (int kk = 0; kk < 4; kk++) {
            uint32_t bh[4][2], bl[4][2];
#pragma unroll
            for (int nf2 = 0; nf2 < 2; nf2++) {
                uint32_t off = (uint32_t)(wn + nf2 * 16 + brow) * 128 + kk * 32 + bcolb;
                off ^= (off >> 3) & 0x70;
                LDSM4(bh[nf2*2+0][0], bh[nf2*2+0][1], bh[nf2*2+1][0], bh[nf2*2+1][1], sBh + off);
                LDSM4(bl[nf2*2+0][0], bl[nf2*2+0][1], bl[nf2*2+1][0], bl[nf2*2+1][1], sBl + off);
            }
#pragma unroll
            for (int mf = 0; mf < 4; mf++) {
                uint32_t off = (uint32_t)(wm + mf * 16 + arow) * 128 + kk * 32 + acolb;
                off ^= (off >> 3) & 0x70;
                uint32_t ah0, ah1, ah2, ah3, al0, al1, al2, al3;
                LDSM4(ah0, ah1, ah2, ah3, sAh + off);
                LDSM4(al0, al1, al2, al3, sAl + off);
#pragma unroll
                for (int nf = 0; nf < 4; nf++) {
                    MMA16816(acc[mf][nf], ah0, ah1, ah2, ah3, bh[nf][0], bh[nf][1]);
                    MMA16816(acc[mf][nf], ah0, ah1, ah2, ah3, bl[nf][0], bl[nf][1]);
                    MMA16816(acc[mf][nf], al0, al1, al2, al3, bh[nf][0], bh[nf][1]);
                }
            }
        }
    }
}

// -------- plain GEMM (output projection): C fp32 [M,N] -----------------------
__global__ void __launch_bounds__(256) mma_gemm(const __nv_bfloat16* __restrict__ Ah_,
                                                const __nv_bfloat16* __restrict__ Al_,
                                                const __nv_bfloat16* __restrict__ Bh_,
                                                const __nv_bfloat16* __restrict__ Bl_,
                                                float* __restrict__ C)
{
    extern __shared__ char smem[];
    const uint32_t sbase = smem_to_u32(smem);
    const int tid = threadIdx.x;
    const int wid = tid >> 5;
    const int lane = tid & 31;
    const int m0 = blockIdx.y * 128;
    const int n0 = blockIdx.x * 128;
    const int wm = (wid & 1) * 64;
    const int wn = (wid >> 1) * 32;
    const int t  = lane >> 3;
    const int li = lane & 7;

    float acc[4][4][4];
    gemm_mainloop(sbase, (const uint4*)Ah_, (const uint4*)Al_,
                  (const uint4*)Bh_, (const uint4*)Bl_,
                  m0, n0, tid, wm, wn,
                  (t & 1) * 8 + li, (t >> 1) * 16,
                  ((t >> 1) & 1) * 8 + li, (t & 1) * 16, acc);

    const int g  = lane >> 2;
    const int tq = lane & 3;
#pragma unroll
    for (int mf = 0; mf < 4; mf++) {
#pragma unroll
        for (int nf = 0; nf < 4; nf++) {
            int rr = m0 + wm + mf * 16 + g;
            int cc = n0 + wn + nf * 8 + tq * 2;
            *(float2*)&C[(size_t)rr * DMODEL + cc]       = make_float2(acc[mf][nf][0], acc[mf][nf][1]);
            *(float2*)&C[(size_t)(rr + 8) * DMODEL + cc] = make_float2(acc[mf][nf][2], acc[mf][nf][3]);
        }
    }
}

// -------- fused QKV GEMM + RoPE + transpose + bf16 split ---------------------
__global__ void __launch_bounds__(256) qkv_gemm(
    const __nv_bfloat16* __restrict__ xh_, const __nv_bfloat16* __restrict__ xl_,
    const __nv_bfloat16* __restrict__ wqh_, const __nv_bfloat16* __restrict__ wql_,
    const __nv_bfloat16* __restrict__ wkh_, const __nv_bfloat16* __restrict__ wkl_,
    const __nv_bfloat16* __restrict__ wvh_, const __nv_bfloat16* __restrict__ wvl_,
    __nv_bfloat16* __restrict__ qh, __nv_bfloat16* __restrict__ ql,
    __nv_bfloat16* __restrict__ kh, __nv_bfloat16* __restrict__ kl,
    __nv_bfloat16* __restrict__ vh, __nv_bfloat16* __restrict__ vl,
    float* __restrict__ kc, float* __restrict__ vc, RopeTab tab)
{
    extern __shared__ char smem[];
    const uint32_t sbase = smem_to_u32(smem);
    const int tid = threadIdx.x;
    const int wid = tid >> 5;
    const int lane = tid & 31;
    const int m0 = blockIdx.y * 128;
    const int n0 = blockIdx.x * 128;
    const int which = blockIdx.z;
    const int wm = (wid & 1) * 64;
    const int wn = (wid >> 1) * 32;
    const int t  = lane >> 3;
    const int li = lane & 7;

    const __nv_bfloat16* Bh_ = (which == 0) ? wqh_ : (which == 1) ? wkh_ : wvh_;
    const __nv_bfloat16* Bl_ = (which == 0) ? wql_ : (which == 1) ? wkl_ : wvl_;

    float acc[4][4][4];
    gemm_mainloop(sbase, (const uint4*)xh_, (const uint4*)xl_,
                  (const uint4*)Bh_, (const uint4*)Bl_,
                  m0, n0, tid, wm, wn,
                  (t & 1) * 8 + li, (t >> 1) * 16,
                  ((t >> 1) & 1) * 8 + li, (t & 1) * 16, acc);

    __nv_bfloat16* H = (which == 0) ? qh : (which == 1) ? kh : vh;
    __nv_bfloat16* L = (which == 0) ? ql : (which == 1) ? kl : vl;

    const int g  = lane >> 2;
    const int tq = lane & 3;
#pragma unroll
    for (int mf = 0; mf < 4; mf++) {
#pragma unroll
        for (int nf = 0; nf < 4; nf++) {
            int cc = n0 + wn + nf * 8 + tq * 2;
            int hh = cc >> 6;
            int d  = cc & 63;
            int p  = d >> 1;
            float fhi = tab.hi[p], flo = tab.lo[p];
#pragma unroll
            for (int r = 0; r < 2; r++) {
                int rr = m0 + wm + mf * 16 + g + r * 8;
                float a = acc[mf][nf][r*2], bv = acc[mf][nf][r*2+1];
                int s  = rr & (SEQ - 1);
                int bb = rr >> 11;
                if (which != 2) {
                    float fs = (float)s;
                    float ang = fmaf(fs, flo, fs * fhi);
                    float c, sn;
                    sincosf(ang, &sn, &c);
                    float na = a * c - bv * sn;
                    float nb = a * sn + bv * c;
                    a = na; bv = nb;
                }
                size_t dst = ((size_t)(bb * NHEADS + hh) * SEQ + s) * HDIM + d;
                store_split2(H, L, dst, a, bv);
                if (which == 1) *(float2*)(kc + dst) = make_float2(a, bv);
                if (which == 2) *(float2*)(vc + dst) = make_float2(a, bv);
            }
        }
    }
}

// ---------------- tensor-core causal flash attention (Bc=64, 2 CTA/SM) -------
#define FQH 0
#define FQL 16384
#define FST 32768
#define FSTAGE 32768
#define FLASH_SMEM (FST + 2*FSTAGE)   // 98304

__device__ __forceinline__ void flash_stage(uint32_t st,
    const uint4* __restrict__ Kh, const uint4* __restrict__ Kl,
    const uint4* __restrict__ Vh, const uint4* __restrict__ Vl,
    int k0, int tid)
{
#pragma unroll
    for (int half = 0; half < 2; half++) {
        int idx = tid + half * 256;      // 0..511
        int row = idx >> 3, q = idx & 7;
        uint32_t off = row * 128 + q * 16;
        off ^= (off >> 3) & 0x70;
        size_t g = (size_t)(k0 + row) * 8 + q;
        cp16(st + off,           Kh + g);
        cp16(st + 8192  + off,   Kl + g);
        cp16(st + 16384 + off,   Vh + g);
        cp16(st + 24576 + off,   Vl + g);
    }
}

__global__ void __launch_bounds__(256, 2) flash_mma(
    const __nv_bfloat16* __restrict__ qh_, const __nv_bfloat16* __restrict__ ql_,
    const __nv_bfloat16* __restrict__ kh_, const __nv_bfloat16* __restrict__ kl_,
    const __nv_bfloat16* __restrict__ vh_, const __nv_bfloat16* __restrict__ vl_,
    __nv_bfloat16* __restrict__ Oh, __nv_bfloat16* __restrict__ Ol)
{
    extern __shared__ char smem[];
    const uint32_t sb = smem_to_u32(smem);
    const int tid = threadIdx.x;
    const int wid = tid >> 5;
    const int lane = tid & 31;
    const int qt = gridDim.x - 1 - blockIdx.x;   // heavy first
    const int h  = blockIdx.y;
    const int b  = blockIdx.z;
    const int q0 = qt * 128;
    const size_t head = (size_t)(b * NHEADS + h) * SEQ;

    const uint4* Qh4 = (const uint4*)qh_ + (head + q0) * 8;
    const uint4* Ql4 = (const uint4*)ql_ + (head + q0) * 8;
    const uint4* Kh4 = (const uint4*)kh_ + head * 8;
    const uint4* Kl4 = (const uint4*)kl_ + head * 8;
    const uint4* Vh4 = (const uint4*)vh_ + head * 8;
    const uint4* Vl4 = (const uint4*)vl_ + head * 8;

    const int t  = lane >> 3;
    const int li = lane & 7;
    const int arow  = (t & 1) * 8 + li;
    const int acolb = (t >> 1) * 16;
    const int brow  = ((t >> 1) & 1) * 8 + li;
    const int bcolb = (t & 1) * 16;
    const int vrow  = (t & 1) * 8 + li;
    const int vcsel = (t >> 1);

    // Q tile (hi+lo)
#pragma unroll
    for (int it = 0; it < 4; it++) {
        int idx = tid + it * 256;
        int row = idx >> 3, q = idx & 7;
        uint32_t off = row * 128 + q * 16;
        off ^= (off >> 3) & 0x70;
        cp16(sb + FQH + off, Qh4 + (size_t)row * 8 + q);
        cp16(sb + FQL + off, Ql4 + (size_t)row * 8 + q);
    }
    flash_stage(sb + FST, Kh4, Kl4, Vh4, Vl4, 0, tid);
    asm volatile("cp.async.commit_group;" ::: "memory");

    const int nkt = 2 * qt + 2;   // 64-key tiles covering keys 0..q0+127

    uint32_t qhA[4][4], qlA[4][4];
    float out[8][4];
#pragma unroll
    for (int nf = 0; nf < 8; nf++)
#pragma unroll
        for (int r = 0; r < 4; r++) out[nf][r] = 0.f;

    float m0 = -1e30f, m1 = -1e30f, l0 = 0.f, l1 = 0.f;
    const int r0g = q0 + wid * 16 + (lane >> 2);
    const int r1g = r0g + 8;

    for (int kt = 0; kt < nkt; kt++) {
        __syncthreads();
        if (kt + 1 < nkt) {
            flash_stage(sb + FST + (uint32_t)((kt + 1) & 1) * FSTAGE,
                        Kh4, Kl4, Vh4, Vl4, (kt + 1) * 64, tid);
            asm volatile("cp.async.commit_group;" ::: "memory");
            asm volatile("cp.async.wait_group 1;" ::: "memory");
        } else {
            asm volatile("cp.async.wait_group 0;" ::: "memory");
        }
        __syncthreads();

        if (kt == 0) {
#pragma unroll
            for (int kk = 0; kk < 4; kk++) {
                uint32_t off = (uint32_t)(wid * 16 + arow) * 128 + kk * 32 + acolb;
                off ^= (off >> 3) & 0x70;
                LDSM4(qhA[kk][0], qhA[kk][1], qhA[kk][2], qhA[kk][3], sb + FQH + off);
                LDSM4(qlA[kk][0], qlA[kk][1], qlA[kk][2], qlA[kk][3], sb + FQL + off);
            }
        }

        const uint32_t st  = sb + FST + (uint32_t)(kt & 1) * FSTAGE;
        const uint32_t sKh = st, sKl = st + 8192, sVh = st + 16384, sVl = st + 24576;

        // ---- S = Q K^T (64 keys) ----
        float sacc[8][4];
#pragma unroll
        for (int nf = 0; nf < 8; nf++)
#pragma unroll
            for (int r = 0; r < 4; r++) sacc[nf][r] = 0.f;

#pragma unroll
        for (int kk = 0; kk < 4; kk++) {
#pragma unroll
            for (int nfp = 0; nfp < 4; nfp++) {
                uint32_t off = (uint32_t)(nfp * 16 + brow) * 128 + kk * 32 + bcolb;
                off ^= (off >> 3) & 0x70;
                uint32_t bh0, bh1, bh2, bh3, bl0, bl1, bl2, bl3;
                LDSM4(bh0, bh1, bh2, bh3, sKh + off);
                LDSM4(bl0, bl1, bl2, bl3, sKl + off);
                MMA16816(sacc[nfp*2],   qhA[kk][0], qhA[kk][1], qhA[kk][2], qhA[kk][3], bh0, bh1);
                MMA16816(sacc[nfp*2],   qhA[kk][0], qhA[kk][1], qhA[kk][2], qhA[kk][3], bl0, bl1);
                MMA16816(sacc[nfp*2],   qlA[kk][0], qlA[kk][1], qlA[kk][2], qlA[kk][3], bh0, bh1);
                MMA16816(sacc[nfp*2+1], qhA[kk][0], qhA[kk][1], qhA[kk][2], qhA[kk][3], bh2, bh3);
                MMA16816(sacc[nfp*2+1], qhA[kk][0], qhA[kk][1], qhA[kk][2], qhA[kk][3], bl2, bl3);
                MMA16816(sacc[nfp*2+1], qlA[kk][0], qlA[kk][1], qlA[kk][2], qlA[kk][3], bh2, bh3);
            }
        }

        // ---- scale + causal mask + row max ----
        const float sc = 0.125f;
        const bool domask = (kt >= nkt - 2);
        float mx0 = -1e30f, mx1 = -1e30f;
#pragma unroll
        for (int nf = 0; nf < 8; nf++) {
            int key = kt * 64 + nf * 8 + (lane & 3) * 2;
            float s0 = sacc[nf][0] * sc;
            float s1 = sacc[nf][1] * sc;
            float s2 = sacc[nf][2] * sc;
            float s3 = sacc[nf][3] * sc;
            if (domask) {
                if (key     > r0g) s0 = -1e30f;
                if (key + 1 > r0g) s1 = -1e30f;
                if (key     > r1g) s2 = -1e30f;
                if (key + 1 > r1g) s3 = -1e30f;
            }
            sacc[nf][0] = s0; sacc[nf][1] = s1; sacc[nf][2] = s2; sacc[nf][3] = s3;
            mx0 = fmaxf(mx0, fmaxf(s0, s1));
            mx1 = fmaxf(mx1, fmaxf(s2, s3));
        }
        mx0 = fmaxf(mx0, __shfl_xor_sync(0xffffffffu, mx0, 1));
        mx0 = fmaxf(mx0, __shfl_xor_sync(0xffffffffu, mx0, 2));
        mx1 = fmaxf(mx1, __shfl_xor_sync(0xffffffffu, mx1, 1));
        mx1 = fmaxf(mx1, __shfl_xor_sync(0xffffffffu, mx1, 2));

        float mn0 = fmaxf(m0, mx0), mn1 = fmaxf(m1, mx1);
        float al0 = __expf(m0 - mn0), al1 = __expf(m1 - mn1);

        // rescale accumulators
#pragma unroll
        for (int nf = 0; nf < 8; nf++) {
            out[nf][0] *= al0; out[nf][1] *= al0;
            out[nf][2] *= al1; out[nf][3] *= al1;
        }

        // ---- exp + P fragments + P.V (interleaved per kk) ----
        float sum0 = 0.f, sum1 = 0.f;
#pragma unroll
        for (int kk = 0; kk < 4; kk++) {
            uint32_t ph[4], pl[4];
#pragma unroll
            for (int half = 0; half < 2; half++) {
                int nf = kk * 2 + half;
                float p0 = __expf(sacc[nf][0] - mn0);
                float p1 = __expf(sacc[nf][1] - mn0);
                float p2 = __expf(sacc[nf][2] - mn1);
                float p3 = __expf(sacc[nf][3] - mn1);
                sum0 += p0 + p1;
                sum1 += p2 + p3;
                __nv_bfloat16 h0 = __float2bfloat16(p0), h1 = __float2bfloat16(p1);
                __nv_bfloat16 h2 = __float2bfloat16(p2), h3 = __float2bfloat16(p3);
                float e0 = p0 - __bfloat162float(h0), e1 = p1 - __bfloat162float(h1);
                float e2 = p2 - __bfloat162float(h2), e3 = p3 - __bfloat162float(h3);
                __nv_bfloat162 ph01 = __halves2bfloat162(h0, h1);
                __nv_bfloat162 ph23 = __halves2bfloat162(h2, h3);
                ph[half*2]     = *(uint32_t*)&ph01;
                ph[half*2 + 1] = *(uint32_t*)&ph23;
                pl[half*2]     = pack_bf16(e0, e1);
                pl[half*2 + 1] = pack_bf16(e2, e3);
            }
#pragma unroll
            for (int jp = 0; jp < 8; jp += 2) {
                uint32_t off = (uint32_t)(kk * 16 + vrow) * 128 + (jp + vcsel) * 16;
                off ^= (off >> 3) & 0x70;
                uint32_t vh0, vh1, vh2, vh3, vl0, vl1, vl2, vl3;
                LDSM4T(vh0, vh1, vh2, vh3, sVh + off);
                LDSM4T(vl0, vl1, vl2, vl3, sVl + off);
                MMA16816(out[jp],   ph[0], ph[1], ph[2], ph[3], vh0, vh1);
                MMA16816(out[jp],   ph[0], ph[1], ph[2], ph[3], vl0, vl1);
                MMA16816(out[jp],   pl[0], pl[1], pl[2], pl[3], vh0, vh1);
                MMA16816(out[jp+1], ph[0], ph[1], ph[2], ph[3], vh2, vh3);
                MMA16816(out[jp+1], ph[0], ph[1], ph[2], ph[3], vl2, vl3);
                MMA16816(out[jp+1], pl[0], pl[1], pl[2], pl[3], vh2, vh3);
            }
        }
        sum0 += __shfl_xor_sync(0xffffffffu, sum0, 1);
        sum0 += __shfl_xor_sync(0xffffffffu, sum0, 2);
        sum1 += __shfl_xor_sync(0xffffffffu, sum1, 1);
        sum1 += __shfl_xor_sync(0xffffffffu, sum1, 2);
        l0 = l0 * al0 + sum0;
        l1 = l1 * al1 + sum1;
        m0 = mn0; m1 = mn1;
    }

    // ---- epilogue ----
    float inv0 = 1.f / l0, inv1 = 1.f / l1;
#pragma unroll
    for (int nf = 0; nf < 8; nf++) {
        int col = h * HDIM + nf * 8 + (lane & 3) * 2;
        size_t i0 = (size_t)(b * SEQ + r0g) * DMODEL + col;
        size_t i1 = (size_t)(b * SEQ + r1g) * DMODEL + col;
        store_split2(Oh, Ol, i0, out[nf][0] * inv0, out[nf][1] * inv0);
        store_split2(Oh, Ol, i1, out[nf][2] * inv1, out[nf][3] * inv1);
    }
}

// ---------------- launcher ---------------------------------------------------
extern "C" void kernel_launch(void* const* d_in, const int* in_sizes, int n_in,
                              void* d_out, int out_size)
{
    const float* x  = (const float*)d_in[0];
    const float* Wq = (const float*)d_in[2];
    const float* Wk = (const float*)d_in[3];
    const float* Wv = (const float*)d_in[4];
    const float* Wo = (const float*)d_in[5];
    float* out = (float*)d_out;

    float *kfb, *vfb;
    cudaGetSymbolAddress((void**)&kfb, g_kfb);
    cudaGetSymbolAddress((void**)&vfb, g_vfb);

    __nv_bfloat16 *xh, *xl, *wqh, *wql, *wkh, *wkl, *wvh, *wvl, *woh, *wol;
    __nv_bfloat16 *qh, *ql, *kh, *kl, *vh, *vl;
    cudaGetSymbolAddress((void**)&xh, g_xh);
    cudaGetSymbolAddress((void**)&xl, g_xl);
    cudaGetSymbolAddress((void**)&wqh, g_wqh);
    cudaGetSymbolAddress((void**)&wql, g_wql);
    cudaGetSymbolAddress((void**)&wkh, g_wkh);
    cudaGetSymbolAddress((void**)&wkl, g_wkl);
    cudaGetSymbolAddress((void**)&wvh, g_wvh);
    cudaGetSymbolAddress((void**)&wvl, g_wvl);
    cudaGetSymbolAddress((void**)&woh, g_woh);
    cudaGetSymbolAddress((void**)&wol, g_wol);
    cudaGetSymbolAddress((void**)&qh, g_qh);
    cudaGetSymbolAddress((void**)&ql, g_ql);
    cudaGetSymbolAddress((void**)&kh, g_kh);
    cudaGetSymbolAddress((void**)&kl, g_kl);
    cudaGetSymbolAddress((void**)&vh, g_vh);
    cudaGetSymbolAddress((void**)&vl, g_vl);

    float* kdst;
    float* vdst;
    if (out_size >= OUTN + 2 * KVN) {
        kdst = out + OUTN;
        vdst = out + OUTN + KVN;
    } else {
        kdst = kfb;
        vdst = vfb;
    }

    cudaFuncSetAttribute(mma_gemm, cudaFuncAttributeMaxDynamicSharedMemorySize, GEMM_SMEM);
    cudaFuncSetAttribute(qkv_gemm, cudaFuncAttributeMaxDynamicSharedMemorySize, GEMM_SMEM);
    cudaFuncSetAttribute(flash_mma, cudaFuncAttributeMaxDynamicSharedMemorySize, FLASH_SMEM);

    RopeTab tab;
    for (int p = 0; p < 32; p++) {
        double invf = exp(-(double)p * (log(10000.0) / 32.0));
        float hi = (float)invf;
        tab.hi[p] = hi;
        tab.lo[p] = (float)(invf - (double)hi);
    }

    // splits: x + 4 weights
    split_kernel<<<OUTN/4/256, 256>>>((const float4*)x, (__nv_bfloat162*)xh, (__nv_bfloat162*)xl, OUTN/4);
    Ptrs4 wp;
    wp.s[0] = (const float4*)Wq; wp.h[0] = (__nv_bfloat162*)wqh; wp.l[0] = (__nv_bfloat162*)wql;
    wp.s[1] = (const float4*)Wk; wp.h[1] = (__nv_bfloat162*)wkh; wp.l[1] = (__nv_bfloat162*)wkl;
    wp.s[2] = (const float4*)Wv; wp.h[2] = (__nv_bfloat162*)wvh; wp.l[2] = (__nv_bfloat162*)wvl;
    wp.s[3] = (const float4*)Wo; wp.h[3] = (__nv_bfloat162*)woh; wp.l[3] = (__nv_bfloat162*)wol;
    dim3 wgrid(WN/4/256, 4);
    wsplit<<<wgrid, 256>>>(wp, WN/4);

    // fused QKV projection + RoPE + split (one launch, 768 CTAs)
    dim3 ggrid(DMODEL / 128, MROWS / 128, 3);   // (8, 32, 3)
    qkv_gemm<<<ggrid, 256, GEMM_SMEM>>>(xh, xl,
                                        wqh, wql, wkh, wkl, wvh, wvl,
                                        qh, ql, kh, kl, vh, vl,
                                        kdst, vdst, tab);

    // tensor-core flash attention -> split bf16 attn output (xh/xl reused)
    dim3 fgrid(SEQ / 128, NHEADS, BATCH);       // (16, 16, 2)
    flash_mma<<<fgrid, 256, FLASH_SMEM>>>(qh, ql, kh, kl, vh, vl, xh, xl);

    // output projection
    dim3 ogrid(DMODEL / 128, MROWS / 128);
    mma_gemm<<<ogrid, 256, GEMM_SMEM>>>(xh, xl, woh, wol, out);
}

// round 7
// speedup vs baseline: 1.1156x; 1.1156x over previous
#include <cuda_runtime.h>
#include <cuda_bf16.h>
#include <math.h>
#include <stdint.h>

// Problem constants
#define BATCH 2
#define SEQ 2048
#define DMODEL 1024
#define NHEADS 16
#define HDIM 64
#define MROWS (BATCH*SEQ)              // 4096
#define OUTN  (BATCH*SEQ*DMODEL)       // 4194304
#define KVN   (BATCH*NHEADS*SEQ*HDIM)  // 4194304
#define WN    (DMODEL*DMODEL)          // 1048576

// ---------------- scratch (device globals; no allocations allowed) ----------
__device__ float g_kfb[KVN];
__device__ float g_vfb[KVN];
__device__ __nv_bfloat16 g_xh[OUTN];
__device__ __nv_bfloat16 g_xl[OUTN];
__device__ __nv_bfloat16 g_wqh[WN], g_wql[WN];
__device__ __nv_bfloat16 g_wkh[WN], g_wkl[WN];
__device__ __nv_bfloat16 g_wvh[WN], g_wvl[WN];
__device__ __nv_bfloat16 g_woh[WN], g_wol[WN];
__device__ __nv_bfloat16 g_qh[KVN], g_ql[KVN];
__device__ __nv_bfloat16 g_kh[KVN], g_kl[KVN];
__device__ __nv_bfloat16 g_vh[KVN], g_vl[KVN];

// ====================== helpers ==============================================
__device__ __forceinline__ uint32_t smem_to_u32(const void* p) {
    uint32_t a;
    asm("{ .reg .u64 t; cvta.to.shared.u64 t, %1; cvt.u32.u64 %0, t; }"
        : "=r"(a) : "l"(p));
    return a;
}

__device__ __forceinline__ void cp16(uint32_t saddr, const void* g) {
    asm volatile("cp.async.cg.shared.global [%0], [%1], 16;"
                 :: "r"(saddr), "l"(g) : "memory");
}

#define LDSM4(r0, r1, r2, r3, addr) \
    asm volatile("ldmatrix.sync.aligned.m8n8.x4.shared.b16 {%0,%1,%2,%3}, [%4];" \
                 : "=r"(r0), "=r"(r1), "=r"(r2), "=r"(r3) : "r"(addr))

#define LDSM4T(r0, r1, r2, r3, addr) \
    asm volatile("ldmatrix.sync.aligned.m8n8.x4.trans.shared.b16 {%0,%1,%2,%3}, [%4];" \
                 : "=r"(r0), "=r"(r1), "=r"(r2), "=r"(r3) : "r"(addr))

#define MMA16816(d, a0, a1, a2, a3, b0, b1) \
    asm volatile("mma.sync.aligned.m16n8k16.row.col.f32.bf16.bf16.f32 " \
                 "{%0,%1,%2,%3}, {%4,%5,%6,%7}, {%8,%9}, {%0,%1,%2,%3};" \
                 : "+f"((d)[0]), "+f"((d)[1]), "+f"((d)[2]), "+f"((d)[3]) \
                 : "r"(a0), "r"(a1), "r"(a2), "r"(a3), "r"(b0), "r"(b1))

__device__ __forceinline__ uint32_t pack_bf16(float a, float b) {
    __nv_bfloat162 v = __halves2bfloat162(__float2bfloat16(a), __float2bfloat16(b));
    return *(uint32_t*)&v;
}

__device__ __forceinline__ void store_split2(__nv_bfloat16* H, __nv_bfloat16* L,
                                             size_t idx, float a, float b) {
    __nv_bfloat16 ha = __float2bfloat16(a), hb = __float2bfloat16(b);
    float ra = a - __bfloat162float(ha), rb = b - __bfloat162float(hb);
    *(__nv_bfloat162*)(H + idx) = __halves2bfloat162(ha, hb);
    *(__nv_bfloat162*)(L + idx) =
        __halves2bfloat162(__float2bfloat16(ra), __float2bfloat16(rb));
}

struct RopeTab { float hi[32]; float lo[32]; };

// ====================== bf16 split conversion ================================
__global__ void split_kernel(const float4* __restrict__ src,
                             __nv_bfloat162* __restrict__ hi,
                             __nv_bfloat162* __restrict__ lo, int n4)
{
    int i = blockIdx.x * blockDim.x + threadIdx.x;
    if (i >= n4) return;
    float4 v = src[i];
    __nv_bfloat16 h0 = __float2bfloat16(v.x);
    __nv_bfloat16 h1 = __float2bfloat16(v.y);
    __nv_bfloat16 h2 = __float2bfloat16(v.z);
    __nv_bfloat16 h3 = __float2bfloat16(v.w);
    float r0 = v.x - __bfloat162float(h0);
    float r1 = v.y - __bfloat162float(h1);
    float r2 = v.z - __bfloat162float(h2);
    float r3 = v.w - __bfloat162float(h3);
    hi[2*i]   = __halves2bfloat162(h0, h1);
    hi[2*i+1] = __halves2bfloat162(h2, h3);
    lo[2*i]   = __halves2bfloat162(__float2bfloat16(r0), __float2bfloat16(r1));
    lo[2*i+1] = __halves2bfloat162(__float2bfloat16(r2), __float2bfloat16(r3));
}

struct Ptrs4 {
    const float4* s[4];
    __nv_bfloat162* h[4];
    __nv_bfloat162* l[4];
};

__global__ void wsplit(Ptrs4 p, int n4)
{
    int i = blockIdx.x * blockDim.x + threadIdx.x;
    int w = blockIdx.y;
    if (i >= n4) return;
    float4 v = p.s[w][i];
    __nv_bfloat16 h0 = __float2bfloat16(v.x);
    __nv_bfloat16 h1 = __float2bfloat16(v.y);
    __nv_bfloat16 h2 = __float2bfloat16(v.z);
    __nv_bfloat16 h3 = __float2bfloat16(v.w);
    float r0 = v.x - __bfloat162float(h0);
    float r1 = v.y - __bfloat162float(h1);
    float r2 = v.z - __bfloat162float(h2);
    float r3 = v.w - __bfloat162float(h3);
    p.h[w][2*i]   = __halves2bfloat162(h0, h1);
    p.h[w][2*i+1] = __halves2bfloat162(h2, h3);
    p.l[w][2*i]   = __halves2bfloat162(__float2bfloat16(r0), __float2bfloat16(r1));
    p.l[w][2*i+1] = __halves2bfloat162(__float2bfloat16(r2), __float2bfloat16(r3));
}

// ====================== mma.sync split-bf16 GEMM core (128x64 tile) ==========
// 2 CTAs/SM: stage = Ah(16K) + Al(16K) + Bh(8K) + Bl(8K) = 48KB, x2 = 96KB
#define TBA 16384
#define TBB 8192
#define STAGE (2*TBA + 2*TBB)      // 49152
#define GEMM_SMEM (2*STAGE)        // 98304
#define NCK 16

__device__ __forceinline__ void stage_load(uint32_t sb,
    const uint4* __restrict__ Ah, const uint4* __restrict__ Al,
    const uint4* __restrict__ Bh, const uint4* __restrict__ Bl,
    int m0, int n0, int c, int tid)
{
    const int q = tid & 7;
    const int r0 = tid >> 3;   // 0..31
    // A tiles: 128 rows
#pragma unroll
    for (int it = 0; it < 4; it++) {
        int row = r0 + it * 32;
        uint32_t off = row * 128 + q * 16;
        off ^= (off >> 3) & 0x70;
        size_t ga = (size_t)(m0 + row) * 128 + c * 8 + q;
        cp16(sb + off,        Ah + ga);
        cp16(sb + TBA + off,  Al + ga);
    }
    // B tiles: 64 rows
#pragma unroll
    for (int it = 0; it < 2; it++) {
        int row = r0 + it * 32;
        uint32_t off = row * 128 + q * 16;
        off ^= (off >> 3) & 0x70;
        size_t gb = (size_t)(n0 + row) * 128 + c * 8 + q;
        cp16(sb + 2*TBA + off,        Bh + gb);
        cp16(sb + 2*TBA + TBB + off,  Bl + gb);
    }
}

// warp layout: wm = (wid&3)*32, wn = (wid>>2)*32; warp tile 32x32
__device__ __forceinline__ void gemm_mainloop(uint32_t sbase,
    const uint4* A4h, const uint4* A4l, const uint4* B4h, const uint4* B4l,
    int m0, int n0, int tid, int wm, int wn,
    int arow, int acolb, int brow, int bcolb, float acc[2][4][4])
{
#pragma unroll
    for (int i = 0; i < 2; i++)
#pragma unroll
        for (int j = 0; j < 4; j++)
#pragma unroll
            for (int r = 0; r < 4; r++) acc[i][j][r] = 0.f;

    stage_load(sbase, A4h, A4l, B4h, B4l, m0, n0, 0, tid);
    asm volatile("cp.async.commit_group;" ::: "memory");

    for (int c = 0; c < NCK; c++) {
        __syncthreads();
        if (c + 1 < NCK) {
            stage_load(sbase + (uint32_t)((c + 1) & 1) * STAGE,
                       A4h, A4l, B4h, B4l, m0, n0, c + 1, tid);
            asm volatile("cp.async.commit_group;" ::: "memory");
            asm volatile("cp.async.wait_group 1;" ::: "memory");
        } else {
            asm volatile("cp.async.wait_group 0;" ::: "memory");
        }
        __syncthreads();

        const uint32_t sb  = sbase + (uint32_t)(c & 1) * STAGE;
        const uint32_t sAh = sb;
        const uint32_t sAl = sb + TBA;
        const uint32_t sBh = sb + 2*TBA;
        const uint32_t sBl = sb + 2*TBA + TBB;

#pragma unroll
        for (int kk = 0; kk < 4; kk++) {
            uint32_t bh[4][2], bl[4][2];
#pragma unroll
            for (int nf2 = 0; nf2 < 2; nf2++) {
                uint32_t off = (uint32_t)(wn + nf2 * 16 + brow) * 128 + kk * 32 + bcolb;
                off ^= (off >> 3) & 0x70;
                LDSM4(bh[nf2*2+0][0], bh[nf2*2+0][1], bh[nf2*2+1][0], bh[nf2*2+1][1], sBh + off);
                LDSM4(bl[nf2*2+0][0], bl[nf2*2+0][1], bl[nf2*2+1][0], bl[nf2*2+1][1], sBl + off);
            }
#pragma unroll
            for (int mf = 0; mf < 2; mf++) {
                uint32_t off = (uint32_t)(wm + mf * 16 + arow) * 128 + kk * 32 + acolb;
                off ^= (off >> 3) & 0x70;
                uint32_t ah0, ah1, ah2, ah3, al0, al1, al2, al3;
                LDSM4(ah0, ah1, ah2, ah3, sAh + off);
                LDSM4(al0, al1, al2, al3, sAl + off);
#pragma unroll
                for (int nf = 0; nf < 4; nf++) {
                    MMA16816(acc[mf][nf], ah0, ah1, ah2, ah3, bh[nf][0], bh[nf][1]);
                    MMA16816(acc[mf][nf], ah0, ah1, ah2, ah3, bl[nf][0], bl[nf][1]);
                    MMA16816(acc[mf][nf], al0, al1, al2, al3, bh[nf][0], bh[nf][1]);
                }
            }
        }
    }
}

// -------- plain GEMM (output projection): C fp32 [M,N] -----------------------
__global__ void __launch_bounds__(256, 2) mma_gemm(const __nv_bfloat16* __restrict__ Ah_,
                                                   const __nv_bfloat16* __restrict__ Al_,
                                                   const __nv_bfloat16* __restrict__ Bh_,
                                                   const __nv_bfloat16* __restrict__ Bl_,
                                                   float* __restrict__ C)
{
    extern __shared__ char smem[];
    const uint32_t sbase = smem_to_u32(smem);
    const int tid = threadIdx.x;
    const int wid = tid >> 5;
    const int lane = tid & 31;
    const int m0 = blockIdx.y * 128;
    const int n0 = blockIdx.x * 64;
    const int wm = (wid & 3) * 32;
    const int wn = (wid >> 2) * 32;
    const int t  = lane >> 3;
    const int li = lane & 7;

    float acc[2][4][4];
    gemm_mainloop(sbase, (const uint4*)Ah_, (const uint4*)Al_,
                  (const uint4*)Bh_, (const uint4*)Bl_,
                  m0, n0, tid, wm, wn,
                  (t & 1) * 8 + li, (t >> 1) * 16,
                  ((t >> 1) & 1) * 8 + li, (t & 1) * 16, acc);

    const int g  = lane >> 2;
    const int tq = lane & 3;
#pragma unroll
    for (int mf = 0; mf < 2; mf++) {
#pragma unroll
        for (int nf = 0; nf < 4; nf++) {
            int rr = m0 + wm + mf * 16 + g;
            int cc = n0 + wn + nf * 8 + tq * 2;
            *(float2*)&C[(size_t)rr * DMODEL + cc]       = make_float2(acc[mf][nf][0], acc[mf][nf][1]);
            *(float2*)&C[(size_t)(rr + 8) * DMODEL + cc] = make_float2(acc[mf][nf][2], acc[mf][nf][3]);
        }
    }
}

// -------- fused QKV GEMM + RoPE + transpose + bf16 split ---------------------
__global__ void __launch_bounds__(256, 2) qkv_gemm(
    const __nv_bfloat16* __restrict__ xh_, const __nv_bfloat16* __restrict__ xl_,
    const __nv_bfloat16* __restrict__ wqh_, const __nv_bfloat16* __restrict__ wql_,
    const __nv_bfloat16* __restrict__ wkh_, const __nv_bfloat16* __restrict__ wkl_,
    const __nv_bfloat16* __restrict__ wvh_, const __nv_bfloat16* __restrict__ wvl_,
    __nv_bfloat16* __restrict__ qh, __nv_bfloat16* __restrict__ ql,
    __nv_bfloat16* __restrict__ kh, __nv_bfloat16* __restrict__ kl,
    __nv_bfloat16* __restrict__ vh, __nv_bfloat16* __restrict__ vl,
    float* __restrict__ kc, float* __restrict__ vc, RopeTab tab)
{
    extern __shared__ char smem[];
    const uint32_t sbase = smem_to_u32(smem);
    const int tid = threadIdx.x;
    const int wid = tid >> 5;
    const int lane = tid & 31;
    const int m0 = blockIdx.y * 128;
    const int n0 = blockIdx.x * 64;
    const int which = blockIdx.z;
    const int wm = (wid & 3) * 32;
    const int wn = (wid >> 2) * 32;
    const int t  = lane >> 3;
    const int li = lane & 7;

    const __nv_bfloat16* Bh_ = (which == 0) ? wqh_ : (which == 1) ? wkh_ : wvh_;
    const __nv_bfloat16* Bl_ = (which == 0) ? wql_ : (which == 1) ? wkl_ : wvl_;

    float acc[2][4][4];
    gemm_mainloop(sbase, (const uint4*)xh_, (const uint4*)xl_,
                  (const uint4*)Bh_, (const uint4*)Bl_,
                  m0, n0, tid, wm, wn,
                  (t & 1) * 8 + li, (t >> 1) * 16,
                  ((t >> 1) & 1) * 8 + li, (t & 1) * 16, acc);

    __nv_bfloat16* H = (which == 0) ? qh : (which == 1) ? kh : vh;
    __nv_bfloat16* L = (which == 0) ? ql : (which == 1) ? kl : vl;

    const int g  = lane >> 2;
    const int tq = lane & 3;
#pragma unroll
    for (int mf = 0; mf < 2; mf++) {
#pragma unroll
        for (int nf = 0; nf < 4; nf++) {
            int cc = n0 + wn + nf * 8 + tq * 2;
            int hh = cc >> 6;
            int d  = cc & 63;
            int p  = d >> 1;
            float fhi = tab.hi[p], flo = tab.lo[p];
#pragma unroll
            for (int r = 0; r < 2; r++) {
                int rr = m0 + wm + mf * 16 + g + r * 8;
                float a = acc[mf][nf][r*2], bv = acc[mf][nf][r*2+1];
                int s  = rr & (SEQ - 1);
                int bb = rr >> 11;
                if (which != 2) {
                    float fs = (float)s;
                    float ang = fmaf(fs, flo, fs * fhi);
                    float c, sn;
                    sincosf(ang, &sn, &c);
                    float na = a * c - bv * sn;
                    float nb = a * sn + bv * c;
                    a = na; bv = nb;
                }
                size_t dst = ((size_t)(bb * NHEADS + hh) * SEQ + s) * HDIM + d;
                store_split2(H, L, dst, a, bv);
                if (which == 1) *(float2*)(kc + dst) = make_float2(a, bv);
                if (which == 2) *(float2*)(vc + dst) = make_float2(a, bv);
            }
        }
    }
}

// ---------------- tensor-core causal flash attention (Bc=128, R5 config) -----
#define FQH 0
#define FQL 16384
#define FST 32768
#define FSTAGE 65536
#define FLASH_SMEM (FST + 2*FSTAGE)   // 163840

__device__ __forceinline__ void flash_stage(uint32_t st,
    const uint4* __restrict__ Kh, const uint4* __restrict__ Kl,
    const uint4* __restrict__ Vh, const uint4* __restrict__ Vl,
    int k0, int tid)
{
#pragma unroll
    for (int it = 0; it < 4; it++) {
        int idx = tid + it * 256;        // 0..1023
        int row = idx >> 3, q = idx & 7;
        uint32_t off = row * 128 + q * 16;
        off ^= (off >> 3) & 0x70;
        size_t g = (size_t)(k0 + row) * 8 + q;
        cp16(st + off,           Kh + g);
        cp16(st + 16384 + off,   Kl + g);
        cp16(st + 32768 + off,   Vh + g);
        cp16(st + 49152 + off,   Vl + g);
    }
}

__global__ void __launch_bounds__(256, 1) flash_mma(
    const __nv_bfloat16* __restrict__ qh_, const __nv_bfloat16* __restrict__ ql_,
    const __nv_bfloat16* __restrict__ kh_, const __nv_bfloat16* __restrict__ kl_,
    const __nv_bfloat16* __restrict__ vh_, const __nv_bfloat16* __restrict__ vl_,
    __nv_bfloat16* __restrict__ Oh, __nv_bfloat16* __restrict__ Ol)
{
    extern __shared__ char smem[];
    const uint32_t sb = smem_to_u32(smem);
    const int tid = threadIdx.x;
    const int wid = tid >> 5;
    const int lane = tid & 31;
    const int qt = gridDim.x - 1 - blockIdx.x;   // heavy first
    const int h  = blockIdx.y;
    const int b  = blockIdx.z;
    const int q0 = qt * 128;
    const size_t head = (size_t)(b * NHEADS + h) * SEQ;

    const uint4* Qh4 = (const uint4*)qh_ + (head + q0) * 8;
    const uint4* Ql4 = (const uint4*)ql_ + (head + q0) * 8;
    const uint4* Kh4 = (const uint4*)kh_ + head * 8;
    const uint4* Kl4 = (const uint4*)kl_ + head * 8;
    const uint4* Vh4 = (const uint4*)vh_ + head * 8;
    const uint4* Vl4 = (const uint4*)vl_ + head * 8;

    const int t  = lane >> 3;
    const int li = lane & 7;
    const int arow  = (t & 1) * 8 + li;
    const int acolb = (t >> 1) * 16;
    const int brow  = ((t >> 1) & 1) * 8 + li;
    const int bcolb = (t & 1) * 16;
    const int vrow  = (t & 1) * 8 + li;
    const int vcsel = (t >> 1);

    // Q tile (hi+lo)
#pragma unroll
    for (int it = 0; it < 4; it++) {
        int idx = tid + it * 256;
        int row = idx >> 3, q = idx & 7;
        uint32_t off = row * 128 + q * 16;
        off ^= (off >> 3) & 0x70;
        cp16(sb + FQH + off, Qh4 + (size_t)row * 8 + q);
        cp16(sb + FQL + off, Ql4 + (size_t)row * 8 + q);
    }
    flash_stage(sb + FST, Kh4, Kl4, Vh4, Vl4, 0, tid);
    asm volatile("cp.async.commit_group;" ::: "memory");

    const int nkt = qt + 1;

    uint32_t qhA[4][4], qlA[4][4];
    float out[8][4];
#pragma unroll
    for (int nf = 0; nf < 8; nf++)
#pragma unroll
        for (int r = 0; r < 4; r++) out[nf][r] = 0.f;

    float m0 = -1e30f, m1 = -1e30f, l0 = 0.f, l1 = 0.f;
    const int r0g = q0 + wid * 16 + (lane >> 2);
    const int r1g = r0g + 8;

    for (int kt = 0; kt < nkt; kt++) {
        __syncthreads();
        if (kt + 1 < nkt) {
            flash_stage(sb + FST + (uint32_t)((kt + 1) & 1) * FSTAGE,
                        Kh4, Kl4, Vh4, Vl4, (kt + 1) * 128, tid);
            asm volatile("cp.async.commit_group;" ::: "memory");
            asm volatile("cp.async.wait_group 1;" ::: "memory");
        } else {
            asm volatile("cp.async.wait_group 0;" ::: "memory");
        }
        __syncthreads();

        if (kt == 0) {
#pragma unroll
            for (int kk = 0; kk < 4; kk++) {
                uint32_t off = (uint32_t)(wid * 16 + arow) * 128 + kk * 32 + acolb;
                off ^= (off >> 3) & 0x70;
                LDSM4(qhA[kk][0], qhA[kk][1], qhA[kk][2], qhA[kk][3], sb + FQH + off);
                LDSM4(qlA[kk][0], qlA[kk][1], qlA[kk][2], qlA[kk][3], sb + FQL + off);
            }
        }

        const uint32_t st  = sb + FST + (uint32_t)(kt & 1) * FSTAGE;
        const uint32_t sKh = st, sKl = st + 16384, sVh = st + 32768, sVl = st + 49152;

        // ---- S = Q K^T (128 keys) ----
        float sacc[16][4];
#pragma unroll
        for (int nf = 0; nf < 16; nf++)
#pragma unroll
            for (int r = 0; r < 4; r++) sacc[nf][r] = 0.f;

#pragma unroll
        for (int kk = 0; kk < 4; kk++) {
#pragma unroll
            for (int nfp = 0; nfp < 8; nfp++) {
                uint32_t off = (uint32_t)(nfp * 16 + brow) * 128 + kk * 32 + bcolb;
                off ^= (off >> 3) & 0x70;
                uint32_t bh0, bh1, bh2, bh3, bl0, bl1, bl2, bl3;
                LDSM4(bh0, bh1, bh2, bh3, sKh + off);
                LDSM4(bl0, bl1, bl2, bl3, sKl + off);
                MMA16816(sacc[nfp*2],   qhA[kk][0], qhA[kk][1], qhA[kk][2], qhA[kk][3], bh0, bh1);
                MMA16816(sacc[nfp*2],   qhA[kk][0], qhA[kk][1], qhA[kk][2], qhA[kk][3], bl0, bl1);
                MMA16816(sacc[nfp*2],   qlA[kk][0], qlA[kk][1], qlA[kk][2], qlA[kk][3], bh0, bh1);
                MMA16816(sacc[nfp*2+1], qhA[kk][0], qhA[kk][1], qhA[kk][2], qhA[kk][3], bh2, bh3);
                MMA16816(sacc[nfp*2+1], qhA[kk][0], qhA[kk][1], qhA[kk][2], qhA[kk][3], bl2, bl3);
                MMA16816(sacc[nfp*2+1], qlA[kk][0], qlA[kk][1], qlA[kk][2], qlA[kk][3], bh2, bh3);
            }
        }

        // ---- scale + causal mask + row max ----
        const float sc = 0.125f;
        const bool domask = (kt == nkt - 1);
        float mx0 = -1e30f, mx1 = -1e30f;
#pragma unroll
        for (int nf = 0; nf < 16; nf++) {
            int key = kt * 128 + nf * 8 + (lane & 3) * 2;
            float s0 = sacc[nf][0] * sc;
            float s1 = sacc[nf][1] * sc;
            float s2 = sacc[nf][2] * sc;
            float s3 = sacc[nf][3] * sc;
            if (domask) {
                if (key     > r0g) s0 = -1e30f;
                if (key + 1 > r0g) s1 = -1e30f;
                if (key     > r1g) s2 = -1e30f;
                if (key + 1 > r1g) s3 = -1e30f;
            }
            sacc[nf][0] = s0; sacc[nf][1] = s1; sacc[nf][2] = s2; sacc[nf][3] = s3;
            mx0 = fmaxf(mx0, fmaxf(s0, s1));
            mx1 = fmaxf(mx1, fmaxf(s2, s3));
        }
        mx0 = fmaxf(mx0, __shfl_xor_sync(0xffffffffu, mx0, 1));
        mx0 = fmaxf(mx0, __shfl_xor_sync(0xffffffffu, mx0, 2));
        mx1 = fmaxf(mx1, __shfl_xor_sync(0xffffffffu, mx1, 1));
        mx1 = fmaxf(mx1, __shfl_xor_sync(0xffffffffu, mx1, 2));

        float mn0 = fmaxf(m0, mx0), mn1 = fmaxf(m1, mx1);
        float al0 = __expf(m0 - mn0), al1 = __expf(m1 - mn1);

        // rescale accumulators
#pragma unroll
        for (int nf = 0; nf < 8; nf++) {
            out[nf][0] *= al0; out[nf][1] *= al0;
            out[nf][2] *= al1; out[nf][3] *= al1;
        }

        // ---- exp + P fragments + P.V (interleaved per kk) ----
        float sum0 = 0.f, sum1 = 0.f;
#pragma unroll
        for (int kk = 0; kk < 8; kk++) {
            uint32_t ph[4], pl[4];
#pragma unroll
            for (int half = 0; half < 2; half++) {
                int nf = kk * 2 + half;
                float p0 = __expf(sacc[nf][0] - mn0);
                float p1 = __expf(sacc[nf][1] - mn0);
                float p2 = __expf(sacc[nf][2] - mn1);
                float p3 = __expf(sacc[nf][3] - mn1);
                sum0 += p0 + p1;
                sum1 += p2 + p3;
                __nv_bfloat16 h0 = __float2bfloat16(p0), h1 = __float2bfloat16(p1);
                __nv_bfloat16 h2 = __float2bfloat16(p2), h3 = __float2bfloat16(p3);
                float e0 = p0 - __bfloat162float(h0), e1 = p1 - __bfloat162float(h1);
                float e2 = p2 - __bfloat162float(h2), e3 = p3 - __bfloat162float(h3);
                __nv_bfloat162 ph01 = __halves2bfloat162(h0, h1);
                __nv_bfloat162 ph23 = __halves2bfloat162(h2, h3);
                ph[half*2]     = *(uint32_t*)&ph01;
                ph[half*2 + 1] = *(uint32_t*)&ph23;
                pl[half*2]     = pack_bf16(e0, e1);
                pl[half*2 + 1] = pack_bf16(e2, e3);
            }
#pragma unroll
            for (int jp = 0; jp < 8; jp += 2) {
                uint32_t off = (uint32_t)(kk * 16 + vrow) * 128 + (jp + vcsel) * 16;
                off ^= (off >> 3) & 0x70;
                uint32_t vh0, vh1, vh2, vh3, vl0, vl1, vl2, vl3;
                LDSM4T(vh0, vh1, vh2, vh3, sVh + off);
                LDSM4T(vl0, vl1, vl2, vl3, sVl + off);
                MMA16816(out[jp],   ph[0], ph[1], ph[2], ph[3], vh0, vh1);
                MMA16816(out[jp],   ph[0], ph[1], ph[2], ph[3], vl0, vl1);
                MMA16816(out[jp],   pl[0], pl[1], pl[2], pl[3], vh0, vh1);
                MMA16816(out[jp+1], ph[0], ph[1], ph[2], ph[3], vh2, vh3);
                MMA16816(out[jp+1], ph[0], ph[1], ph[2], ph[3], vl2, vl3);
                MMA16816(out[jp+1], pl[0], pl[1], pl[2], pl[3], vh2, vh3);
            }
        }
        sum0 += __shfl_xor_sync(0xffffffffu, sum0, 1);
        sum0 += __shfl_xor_sync(0xffffffffu, sum0, 2);
        sum1 += __shfl_xor_sync(0xffffffffu, sum1, 1);
        sum1 += __shfl_xor_sync(0xffffffffu, sum1, 2);
        l0 = l0 * al0 + sum0;
        l1 = l1 * al1 + sum1;
        m0 = mn0; m1 = mn1;
    }

    // ---- epilogue ----
    float inv0 = 1.f / l0, inv1 = 1.f / l1;
#pragma unroll
    for (int nf = 0; nf < 8; nf++) {
        int col = h * HDIM + nf * 8 + (lane & 3) * 2;
        size_t i0 = (size_t)(b * SEQ + r0g) * DMODEL + col;
        size_t i1 = (size_t)(b * SEQ + r1g) * DMODEL + col;
        store_split2(Oh, Ol, i0, out[nf][0] * inv0, out[nf][1] * inv0);
        store_split2(Oh, Ol, i1, out[nf][2] * inv1, out[nf][3] * inv1);
    }
}

// ---------------- launcher ---------------------------------------------------
extern "C" void kernel_launch(void* const* d_in, const int* in_sizes, int n_in,
                              void* d_out, int out_size)
{
    const float* x  = (const float*)d_in[0];
    const float* Wq = (const float*)d_in[2];
    const float* Wk = (const float*)d_in[3];
    const float* Wv = (const float*)d_in[4];
    const float* Wo = (const float*)d_in[5];
    float* out = (float*)d_out;

    float *kfb, *vfb;
    cudaGetSymbolAddress((void**)&kfb, g_kfb);
    cudaGetSymbolAddress((void**)&vfb, g_vfb);

    __nv_bfloat16 *xh, *xl, *wqh, *wql, *wkh, *wkl, *wvh, *wvl, *woh, *wol;
    __nv_bfloat16 *qh, *ql, *kh, *kl, *vh, *vl;
    cudaGetSymbolAddress((void**)&xh, g_xh);
    cudaGetSymbolAddress((void**)&xl, g_xl);
    cudaGetSymbolAddress((void**)&wqh, g_wqh);
    cudaGetSymbolAddress((void**)&wql, g_wql);
    cudaGetSymbolAddress((void**)&wkh, g_wkh);
    cudaGetSymbolAddress((void**)&wkl, g_wkl);
    cudaGetSymbolAddress((void**)&wvh, g_wvh);
    cudaGetSymbolAddress((void**)&wvl, g_wvl);
    cudaGetSymbolAddress((void**)&woh, g_woh);
    cudaGetSymbolAddress((void**)&wol, g_wol);
    cudaGetSymbolAddress((void**)&qh, g_qh);
    cudaGetSymbolAddress((void**)&ql, g_ql);
    cudaGetSymbolAddress((void**)&kh, g_kh);
    cudaGetSymbolAddress((void**)&kl, g_kl);
    cudaGetSymbolAddress((void**)&vh, g_vh);
    cudaGetSymbolAddress((void**)&vl, g_vl);

    float* kdst;
    float* vdst;
    if (out_size >= OUTN + 2 * KVN) {
        kdst = out + OUTN;
        vdst = out + OUTN + KVN;
    } else {
        kdst = kfb;
        vdst = vfb;
    }

    cudaFuncSetAttribute(mma_gemm, cudaFuncAttributeMaxDynamicSharedMemorySize, GEMM_SMEM);
    cudaFuncSetAttribute(qkv_gemm, cudaFuncAttributeMaxDynamicSharedMemorySize, GEMM_SMEM);
    cudaFuncSetAttribute(flash_mma, cudaFuncAttributeMaxDynamicSharedMemorySize, FLASH_SMEM);

    RopeTab tab;
    for (int p = 0; p < 32; p++) {
        double invf = exp(-(double)p * (log(10000.0) / 32.0));
        float hi = (float)invf;
        tab.hi[p] = hi;
        tab.lo[p] = (float)(invf - (double)hi);
    }

    // splits: x + 4 weights
    split_kernel<<<OUTN/4/256, 256>>>((const float4*)x, (__nv_bfloat162*)xh, (__nv_bfloat162*)xl, OUTN/4);
    Ptrs4 wp;
    wp.s[0] = (const float4*)Wq; wp.h[0] = (__nv_bfloat162*)wqh; wp.l[0] = (__nv_bfloat162*)wql;
    wp.s[1] = (const float4*)Wk; wp.h[1] = (__nv_bfloat162*)wkh; wp.l[1] = (__nv_bfloat162*)wkl;
    wp.s[2] = (const float4*)Wv; wp.h[2] = (__nv_bfloat162*)wvh; wp.l[2] = (__nv_bfloat162*)wvl;
    wp.s[3] = (const float4*)Wo; wp.h[3] = (__nv_bfloat162*)woh; wp.l[3] = (__nv_bfloat162*)wol;
    dim3 wgrid(WN/4/256, 4);
    wsplit<<<wgrid, 256>>>(wp, WN/4);

    // fused QKV projection + RoPE + split (128x64 tiles, 2 CTA/SM)
    dim3 ggrid(DMODEL / 64, MROWS / 128, 3);   // (16, 32, 3) = 1536 CTAs
    qkv_gemm<<<ggrid, 256, GEMM_SMEM>>>(xh, xl,
                                        wqh, wql, wkh, wkl, wvh, wvl,
                                        qh, ql, kh, kl, vh, vl,
                                        kdst, vdst, tab);

    // tensor-core flash attention (R5 config) -> split bf16 attn output
    dim3 fgrid(SEQ / 128, NHEADS, BATCH);      // (16, 16, 2)
    flash_mma<<<fgrid, 256, FLASH_SMEM>>>(qh, ql, kh, kl, vh, vl, xh, xl);

    // output projection (128x64 tiles, 2 CTA/SM)
    dim3 ogrid(DMODEL / 64, MROWS / 128);      // (16, 32) = 512 CTAs
    mma_gemm<<<ogrid, 256, GEMM_SMEM>>>(xh, xl, woh, wol, out);
}

// round 8
// speedup vs baseline: 1.2551x; 1.1250x over previous
#include <cuda_runtime.h>
#include <cuda_bf16.h>
#include <cuda_fp16.h>
#include <math.h>
#include <stdint.h>

// Problem constants
#define BATCH 2
#define SEQ 2048
#define DMODEL 1024
#define NHEADS 16
#define HDIM 64
#define MROWS (BATCH*SEQ)              // 4096
#define OUTN  (BATCH*SEQ*DMODEL)       // 4194304
#define KVN   (BATCH*NHEADS*SEQ*HDIM)  // 4194304
#define WN    (DMODEL*DMODEL)          // 1048576

// ---------------- scratch (device globals; no allocations allowed) ----------
__device__ float g_kfb[KVN];
__device__ float g_vfb[KVN];
__device__ __nv_bfloat16 g_xh[OUTN];
__device__ __nv_bfloat16 g_xl[OUTN];
__device__ __nv_bfloat16 g_wqh[WN], g_wql[WN];
__device__ __nv_bfloat16 g_wkh[WN], g_wkl[WN];
__device__ __nv_bfloat16 g_wvh[WN], g_wvl[WN];
__device__ __nv_bfloat16 g_woh[WN], g_wol[WN];
__device__ __nv_bfloat16 g_qh[KVN], g_ql[KVN];
__device__ __nv_bfloat16 g_kh[KVN], g_kl[KVN];
__device__ __half g_vhf[KVN];          // V in single fp16 for flash PV

// ====================== helpers ==============================================
__device__ __forceinline__ uint32_t smem_to_u32(const void* p) {
    uint32_t a;
    asm("{ .reg .u64 t; cvta.to.shared.u64 t, %1; cvt.u32.u64 %0, t; }"
        : "=r"(a) : "l"(p));
    return a;
}

__device__ __forceinline__ void cp16(uint32_t saddr, const void* g) {
    asm volatile("cp.async.cg.shared.global [%0], [%1], 16;"
                 :: "r"(saddr), "l"(g) : "memory");
}

#define LDSM4(r0, r1, r2, r3, addr) \
    asm volatile("ldmatrix.sync.aligned.m8n8.x4.shared.b16 {%0,%1,%2,%3}, [%4];" \
                 : "=r"(r0), "=r"(r1), "=r"(r2), "=r"(r3) : "r"(addr))

#define LDSM4T(r0, r1, r2, r3, addr) \
    asm volatile("ldmatrix.sync.aligned.m8n8.x4.trans.shared.b16 {%0,%1,%2,%3}, [%4];" \
                 : "=r"(r0), "=r"(r1), "=r"(r2), "=r"(r3) : "r"(addr))

#define MMA16816(d, a0, a1, a2, a3, b0, b1) \
    asm volatile("mma.sync.aligned.m16n8k16.row.col.f32.bf16.bf16.f32 " \
                 "{%0,%1,%2,%3}, {%4,%5,%6,%7}, {%8,%9}, {%0,%1,%2,%3};" \
                 : "+f"((d)[0]), "+f"((d)[1]), "+f"((d)[2]), "+f"((d)[3]) \
                 : "r"(a0), "r"(a1), "r"(a2), "r"(a3), "r"(b0), "r"(b1))

#define MMA16816F16(d, a0, a1, a2, a3, b0, b1) \
    asm volatile("mma.sync.aligned.m16n8k16.row.col.f32.f16.f16.f32 " \
                 "{%0,%1,%2,%3}, {%4,%5,%6,%7}, {%8,%9}, {%0,%1,%2,%3};" \
                 : "+f"((d)[0]), "+f"((d)[1]), "+f"((d)[2]), "+f"((d)[3]) \
                 : "r"(a0), "r"(a1), "r"(a2), "r"(a3), "r"(b0), "r"(b1))

__device__ __forceinline__ void store_split2(__nv_bfloat16* H, __nv_bfloat16* L,
                                             size_t idx, float a, float b) {
    __nv_bfloat16 ha = __float2bfloat16(a), hb = __float2bfloat16(b);
    float ra = a - __bfloat162float(ha), rb = b - __bfloat162float(hb);
    *(__nv_bfloat162*)(H + idx) = __halves2bfloat162(ha, hb);
    *(__nv_bfloat162*)(L + idx) =
        __halves2bfloat162(__float2bfloat16(ra), __float2bfloat16(rb));
}

struct RopeTab { float hi[32]; float lo[32]; };

// ====================== bf16 split conversion ================================
__global__ void split_kernel(const float4* __restrict__ src,
                             __nv_bfloat162* __restrict__ hi,
                             __nv_bfloat162* __restrict__ lo, int n4)
{
    int i = blockIdx.x * blockDim.x + threadIdx.x;
    if (i >= n4) return;
    float4 v = src[i];
    __nv_bfloat16 h0 = __float2bfloat16(v.x);
    __nv_bfloat16 h1 = __float2bfloat16(v.y);
    __nv_bfloat16 h2 = __float2bfloat16(v.z);
    __nv_bfloat16 h3 = __float2bfloat16(v.w);
    float r0 = v.x - __bfloat162float(h0);
    float r1 = v.y - __bfloat162float(h1);
    float r2 = v.z - __bfloat162float(h2);
    float r3 = v.w - __bfloat162float(h3);
    hi[2*i]   = __halves2bfloat162(h0, h1);
    hi[2*i+1] = __halves2bfloat162(h2, h3);
    lo[2*i]   = __halves2bfloat162(__float2bfloat16(r0), __float2bfloat16(r1));
    lo[2*i+1] = __halves2bfloat162(__float2bfloat16(r2), __float2bfloat16(r3));
}

struct Ptrs4 {
    const float4* s[4];
    __nv_bfloat162* h[4];
    __nv_bfloat162* l[4];
};

__global__ void wsplit(Ptrs4 p, int n4)
{
    int i = blockIdx.x * blockDim.x + threadIdx.x;
    int w = blockIdx.y;
    if (i >= n4) return;
    float4 v = p.s[w][i];
    __nv_bfloat16 h0 = __float2bfloat16(v.x);
    __nv_bfloat16 h1 = __float2bfloat16(v.y);
    __nv_bfloat16 h2 = __float2bfloat16(v.z);
    __nv_bfloat16 h3 = __float2bfloat16(v.w);
    float r0 = v.x - __bfloat162float(h0);
    float r1 = v.y - __bfloat162float(h1);
    float r2 = v.z - __bfloat162float(h2);
    float r3 = v.w - __bfloat162float(h3);
    p.h[w][2*i]   = __halves2bfloat162(h0, h1);
    p.h[w][2*i+1] = __halves2bfloat162(h2, h3);
    p.l[w][2*i]   = __halves2bfloat162(__float2bfloat16(r0), __float2bfloat16(r1));
    p.l[w][2*i+1] = __halves2bfloat162(__float2bfloat16(r2), __float2bfloat16(r3));
}

// ====================== mma.sync split-bf16 GEMM core (128x64 tile) ==========
#define TBA 16384
#define TBB 8192
#define STAGE (2*TBA + 2*TBB)      // 49152
#define GEMM_SMEM (2*STAGE)        // 98304
#define NCK 16

__device__ __forceinline__ void stage_load(uint32_t sb,
    const uint4* __restrict__ Ah, const uint4* __restrict__ Al,
    const uint4* __restrict__ Bh, const uint4* __restrict__ Bl,
    int m0, int n0, int c, int tid)
{
    const int q = tid & 7;
    const int r0 = tid >> 3;   // 0..31
#pragma unroll
    for (int it = 0; it < 4; it++) {
        int row = r0 + it * 32;
        uint32_t off = row * 128 + q * 16;
        off ^= (off >> 3) & 0x70;
        size_t ga = (size_t)(m0 + row) * 128 + c * 8 + q;
        cp16(sb + off,        Ah + ga);
        cp16(sb + TBA + off,  Al + ga);
    }
#pragma unroll
    for (int it = 0; it < 2; it++) {
        int row = r0 + it * 32;
        uint32_t off = row * 128 + q * 16;
        off ^= (off >> 3) & 0x70;
        size_t gb = (size_t)(n0 + row) * 128 + c * 8 + q;
        cp16(sb + 2*TBA + off,        Bh + gb);
        cp16(sb + 2*TBA + TBB + off,  Bl + gb);
    }
}

__device__ __forceinline__ void gemm_mainloop(uint32_t sbase,
    const uint4* A4h, const uint4* A4l, const uint4* B4h, const uint4* B4l,
    int m0, int n0, int tid, int wm, int wn,
    int arow, int acolb, int brow, int bcolb, float acc[2][4][4])
{
#pragma unroll
    for (int i = 0; i < 2; i++)
#pragma unroll
        for (int j = 0; j < 4; j++)
#pragma unroll
            for (int r = 0; r < 4; r++) acc[i][j][r] = 0.f;

    stage_load(sbase, A4h, A4l, B4h, B4l, m0, n0, 0, tid);
    asm volatile("cp.async.commit_group;" ::: "memory");

    for (int c = 0; c < NCK; c++) {
        __syncthreads();
        if (c + 1 < NCK) {
            stage_load(sbase + (uint32_t)((c + 1) & 1) * STAGE,
                       A4h, A4l, B4h, B4l, m0, n0, c + 1, tid);
            asm volatile("cp.async.commit_group;" ::: "memory");
            asm volatile("cp.async.wait_group 1;" ::: "memory");
        } else {
            asm volatile("cp.async.wait_group 0;" ::: "memory");
        }
        __syncthreads();

        const uint32_t sb  = sbase + (uint32_t)(c & 1) * STAGE;
        const uint32_t sAh = sb;
        const uint32_t sAl = sb + TBA;
        const uint32_t sBh = sb + 2*TBA;
        const uint32_t sBl = sb + 2*TBA + TBB;

#pragma unroll
        for (int kk = 0; kk < 4; kk++) {
            uint32_t bh[4][2], bl[4][2];
#pragma unroll
            for (int nf2 = 0; nf2 < 2; nf2++) {
                uint32_t off = (uint32_t)(wn + nf2 * 16 + brow) * 128 + kk * 32 + bcolb;
                off ^= (off >> 3) & 0x70;
                LDSM4(bh[nf2*2+0][0], bh[nf2*2+0][1], bh[nf2*2+1][0], bh[nf2*2+1][1], sBh + off);
                LDSM4(bl[nf2*2+0][0], bl[nf2*2+0][1], bl[nf2*2+1][0], bl[nf2*2+1][1], sBl + off);
            }
#pragma unroll
            for (int mf = 0; mf < 2; mf++) {
                uint32_t off = (uint32_t)(wm + mf * 16 + arow) * 128 + kk * 32 + acolb;
                off ^= (off >> 3) & 0x70;
                uint32_t ah0, ah1, ah2, ah3, al0, al1, al2, al3;
                LDSM4(ah0, ah1, ah2, ah3, sAh + off);
                LDSM4(al0, al1, al2, al3, sAl + off);
#pragma unroll
                for (int nf = 0; nf < 4; nf++) {
                    MMA16816(acc[mf][nf], ah0, ah1, ah2, ah3, bh[nf][0], bh[nf][1]);
                    MMA16816(acc[mf][nf], ah0, ah1, ah2, ah3, bl[nf][0], bl[nf][1]);
                    MMA16816(acc[mf][nf], al0, al1, al2, al3, bh[nf][0], bh[nf][1]);
                }
            }
        }
    }
}

// -------- plain GEMM (output projection): C fp32 [M,N] -----------------------
__global__ void __launch_bounds__(256, 2) mma_gemm(const __nv_bfloat16* __restrict__ Ah_,
                                                   const __nv_bfloat16* __restrict__ Al_,
                                                   const __nv_bfloat16* __restrict__ Bh_,
                                                   const __nv_bfloat16* __restrict__ Bl_,
                                                   float* __restrict__ C)
{
    extern __shared__ char smem[];
    const uint32_t sbase = smem_to_u32(smem);
    const int tid = threadIdx.x;
    const int wid = tid >> 5;
    const int lane = tid & 31;
    const int m0 = blockIdx.y * 128;
    const int n0 = blockIdx.x * 64;
    const int wm = (wid & 3) * 32;
    const int wn = (wid >> 2) * 32;
    const int t  = lane >> 3;
    const int li = lane & 7;

    float acc[2][4][4];
    gemm_mainloop(sbase, (const uint4*)Ah_, (const uint4*)Al_,
                  (const uint4*)Bh_, (const uint4*)Bl_,
                  m0, n0, tid, wm, wn,
                  (t & 1) * 8 + li, (t >> 1) * 16,
                  ((t >> 1) & 1) * 8 + li, (t & 1) * 16, acc);

    const int g  = lane >> 2;
    const int tq = lane & 3;
#pragma unroll
    for (int mf = 0; mf < 2; mf++) {
#pragma unroll
        for (int nf = 0; nf < 4; nf++) {
            int rr = m0 + wm + mf * 16 + g;
            int cc = n0 + wn + nf * 8 + tq * 2;
            *(float2*)&C[(size_t)rr * DMODEL + cc]       = make_float2(acc[mf][nf][0], acc[mf][nf][1]);
            *(float2*)&C[(size_t)(rr + 8) * DMODEL + cc] = make_float2(acc[mf][nf][2], acc[mf][nf][3]);
        }
    }
}

// -------- fused QKV GEMM + RoPE + transpose + split/fp16 stores ---------------
__global__ void __launch_bounds__(256, 2) qkv_gemm(
    const __nv_bfloat16* __restrict__ xh_, const __nv_bfloat16* __restrict__ xl_,
    const __nv_bfloat16* __restrict__ wqh_, const __nv_bfloat16* __restrict__ wql_,
    const __nv_bfloat16* __restrict__ wkh_, const __nv_bfloat16* __restrict__ wkl_,
    const __nv_bfloat16* __restrict__ wvh_, const __nv_bfloat16* __restrict__ wvl_,
    __nv_bfloat16* __restrict__ qh, __nv_bfloat16* __restrict__ ql,
    __nv_bfloat16* __restrict__ kh, __nv_bfloat16* __restrict__ kl,
    __half* __restrict__ vhf,
    float* __restrict__ kc, float* __restrict__ vc, RopeTab tab)
{
    extern __shared__ char smem[];
    const uint32_t sbase = smem_to_u32(smem);
    const int tid = threadIdx.x;
    const int wid = tid >> 5;
    const int lane = tid & 31;
    const int m0 = blockIdx.y * 128;
    const int n0 = blockIdx.x * 64;
    const int which = blockIdx.z;
    const int wm = (wid & 3) * 32;
    const int wn = (wid >> 2) * 32;
    const int t  = lane >> 3;
    const int li = lane & 7;

    const __nv_bfloat16* Bh_ = (which == 0) ? wqh_ : (which == 1) ? wkh_ : wvh_;
    const __nv_bfloat16* Bl_ = (which == 0) ? wql_ : (which == 1) ? wkl_ : wvl_;

    float acc[2][4][4];
    gemm_mainloop(sbase, (const uint4*)xh_, (const uint4*)xl_,
                  (const uint4*)Bh_, (const uint4*)Bl_,
                  m0, n0, tid, wm, wn,
                  (t & 1) * 8 + li, (t >> 1) * 16,
                  ((t >> 1) & 1) * 8 + li, (t & 1) * 16, acc);

    const int g  = lane >> 2;
    const int tq = lane & 3;
#pragma unroll
    for (int mf = 0; mf < 2; mf++) {
#pragma unroll
        for (int nf = 0; nf < 4; nf++) {
            int cc = n0 + wn + nf * 8 + tq * 2;
            int hh = cc >> 6;
            int d  = cc & 63;
            int p  = d >> 1;
            float fhi = tab.hi[p], flo = tab.lo[p];
#pragma unroll
            for (int r = 0; r < 2; r++) {
                int rr = m0 + wm + mf * 16 + g + r * 8;
                float a = acc[mf][nf][r*2], bv = acc[mf][nf][r*2+1];
                int s  = rr & (SEQ - 1);
                int bb = rr >> 11;
                size_t dst = ((size_t)(bb * NHEADS + hh) * SEQ + s) * HDIM + d;
                if (which == 2) {
                    *(float2*)(vc + dst) = make_float2(a, bv);
                    *(__half2*)(vhf + dst) = __floats2half2_rn(a, bv);
                } else {
                    float fs = (float)s;
                    float ang = fmaf(fs, flo, fs * fhi);
                    float c, sn;
                    sincosf(ang, &sn, &c);
                    float na = a * c - bv * sn;
                    float nb = a * sn + bv * c;
                    if (which == 0) {
                        store_split2(qh, ql, dst, na, nb);
                    } else {
                        store_split2(kh, kl, dst, na, nb);
                        *(float2*)(kc + dst) = make_float2(na, nb);
                    }
                }
            }
        }
    }
}

// ---------------- tensor-core causal flash attention (Bc=128) ----------------
// Stage: Kh(16K) + Kl(16K) + Vh fp16(16K) = 48KB; Q hi/lo 32KB; total 128KB
#define FQH 0
#define FQL 16384
#define FST 32768
#define FSTAGE 49152
#define FLASH_SMEM (FST + 2*FSTAGE)   // 131072

__device__ __forceinline__ void flash_stage(uint32_t st,
    const uint4* __restrict__ Kh, const uint4* __restrict__ Kl,
    const uint4* __restrict__ Vh,
    int k0, int tid)
{
#pragma unroll
    for (int it = 0; it < 4; it++) {
        int idx = tid + it * 256;        // 0..1023
        int row = idx >> 3, q = idx & 7;
        uint32_t off = row * 128 + q * 16;
        off ^= (off >> 3) & 0x70;
        size_t g = (size_t)(k0 + row) * 8 + q;
        cp16(st + off,           Kh + g);
        cp16(st + 16384 + off,   Kl + g);
        cp16(st + 32768 + off,   Vh + g);
    }
}

__global__ void __launch_bounds__(256, 1) flash_mma(
    const __nv_bfloat16* __restrict__ qh_, const __nv_bfloat16* __restrict__ ql_,
    const __nv_bfloat16* __restrict__ kh_, const __nv_bfloat16* __restrict__ kl_,
    const __half* __restrict__ vhf_,
    __nv_bfloat16* __restrict__ Oh, __nv_bfloat16* __restrict__ Ol)
{
    extern __shared__ char smem[];
    const uint32_t sb = smem_to_u32(smem);
    const int tid = threadIdx.x;
    const int wid = tid >> 5;
    const int lane = tid & 31;
    const int qt = gridDim.x - 1 - blockIdx.x;   // heavy first
    const int h  = blockIdx.y;
    const int b  = blockIdx.z;
    const int q0 = qt * 128;
    const size_t head = (size_t)(b * NHEADS + h) * SEQ;

    const uint4* Qh4 = (const uint4*)qh_ + (head + q0) * 8;
    const uint4* Ql4 = (const uint4*)ql_ + (head + q0) * 8;
    const uint4* Kh4 = (const uint4*)kh_ + head * 8;
    const uint4* Kl4 = (const uint4*)kl_ + head * 8;
    const uint4* Vh4 = (const uint4*)vhf_ + head * 8;

    const int t  = lane >> 3;
    const int li = lane & 7;
    const int arow  = (t & 1) * 8 + li;
    const int acolb = (t >> 1) * 16;
    const int brow  = ((t >> 1) & 1) * 8 + li;
    const int bcolb = (t & 1) * 16;
    const int vrow  = (t & 1) * 8 + li;
    const int vcsel = (t >> 1);

    // Q tile (hi+lo)
#pragma unroll
    for (int it = 0; it < 4; it++) {
        int idx = tid + it * 256;
        int row = idx >> 3, q = idx & 7;
        uint32_t off = row * 128 + q * 16;
        off ^= (off >> 3) & 0x70;
        cp16(sb + FQH + off, Qh4 + (size_t)row * 8 + q);
        cp16(sb + FQL + off, Ql4 + (size_t)row * 8 + q);
    }
    flash_stage(sb + FST, Kh4, Kl4, Vh4, 0, tid);
    asm volatile("cp.async.commit_group;" ::: "memory");

    const int nkt = qt + 1;

    uint32_t qhA[4][4], qlA[4][4];
    float out[8][4];
#pragma unroll
    for (int nf = 0; nf < 8; nf++)
#pragma unroll
        for (int r = 0; r < 4; r++) out[nf][r] = 0.f;

    float m0 = -1e30f, m1 = -1e30f, l0 = 0.f, l1 = 0.f;
    const int r0g = q0 + wid * 16 + (lane >> 2);
    const int r1g = r0g + 8;

    for (int kt = 0; kt < nkt; kt++) {
        __syncthreads();
        if (kt + 1 < nkt) {
            flash_stage(sb + FST + (uint32_t)((kt + 1) & 1) * FSTAGE,
                        Kh4, Kl4, Vh4, (kt + 1) * 128, tid);
            asm volatile("cp.async.commit_group;" ::: "memory");
            asm volatile("cp.async.wait_group 1;" ::: "memory");
        } else {
            asm volatile("cp.async.wait_group 0;" ::: "memory");
        }
        __syncthreads();

        if (kt == 0) {
#pragma unroll
            for (int kk = 0; kk < 4; kk++) {
                uint32_t off = (uint32_t)(wid * 16 + arow) * 128 + kk * 32 + acolb;
                off ^= (off >> 3) & 0x70;
                LDSM4(qhA[kk][0], qhA[kk][1], qhA[kk][2], qhA[kk][3], sb + FQH + off);
                LDSM4(qlA[kk][0], qlA[kk][1], qlA[kk][2], qlA[kk][3], sb + FQL + off);
            }
        }

        const uint32_t st  = sb + FST + (uint32_t)(kt & 1) * FSTAGE;
        const uint32_t sKh = st, sKl = st + 16384, sVh = st + 32768;

        // ---- S = Q K^T (128 keys, 3-term bf16 split) ----
        float sacc[16][4];
#pragma unroll
        for (int nf = 0; nf < 16; nf++)
#pragma unroll
            for (int r = 0; r < 4; r++) sacc[nf][r] = 0.f;

#pragma unroll
        for (int kk = 0; kk < 4; kk++) {
#pragma unroll
            for (int nfp = 0; nfp < 8; nfp++) {
                uint32_t off = (uint32_t)(nfp * 16 + brow) * 128 + kk * 32 + bcolb;
                off ^= (off >> 3) & 0x70;
                uint32_t bh0, bh1, bh2, bh3, bl0, bl1, bl2, bl3;
                LDSM4(bh0, bh1, bh2, bh3, sKh + off);
                LDSM4(bl0, bl1, bl2, bl3, sKl + off);
                MMA16816(sacc[nfp*2],   qhA[kk][0], qhA[kk][1], qhA[kk][2], qhA[kk][3], bh0, bh1);
                MMA16816(sacc[nfp*2],   qhA[kk][0], qhA[kk][1], qhA[kk][2], qhA[kk][3], bl0, bl1);
                MMA16816(sacc[nfp*2],   qlA[kk][0], qlA[kk][1], qlA[kk][2], qlA[kk][3], bh0, bh1);
                MMA16816(sacc[nfp*2+1], qhA[kk][0], qhA[kk][1], qhA[kk][2], qhA[kk][3], bh2, bh3);
                MMA16816(sacc[nfp*2+1], qhA[kk][0], qhA[kk][1], qhA[kk][2], qhA[kk][3], bl2, bl3);
                MMA16816(sacc[nfp*2+1], qlA[kk][0], qlA[kk][1], qlA[kk][2], qlA[kk][3], bh2, bh3);
            }
        }

        // ---- scale + causal mask + row max ----
        const float sc = 0.125f;
        const bool domask = (kt == nkt - 1);
        float mx0 = -1e30f, mx1 = -1e30f;
#pragma unroll
        for (int nf = 0; nf < 16; nf++) {
            int key = kt * 128 + nf * 8 + (lane & 3) * 2;
            float s0 = sacc[nf][0] * sc;
            float s1 = sacc[nf][1] * sc;
            float s2 = sacc[nf][2] * sc;
            float s3 = sacc[nf][3] * sc;
            if (domask) {
                if (key     > r0g) s0 = -1e30f;
                if (key + 1 > r0g) s1 = -1e30f;
                if (key     > r1g) s2 = -1e30f;
                if (key + 1 > r1g) s3 = -1e30f;
            }
            sacc[nf][0] = s0; sacc[nf][1] = s1; sacc[nf][2] = s2; sacc[nf][3] = s3;
            mx0 = fmaxf(mx0, fmaxf(s0, s1));
            mx1 = fmaxf(mx1, fmaxf(s2, s3));
        }
        mx0 = fmaxf(mx0, __shfl_xor_sync(0xffffffffu, mx0, 1));
        mx0 = fmaxf(mx0, __shfl_xor_sync(0xffffffffu, mx0, 2));
        mx1 = fmaxf(mx1, __shfl_xor_sync(0xffffffffu, mx1, 1));
        mx1 = fmaxf(mx1, __shfl_xor_sync(0xffffffffu, mx1, 2));

        float mn0 = fmaxf(m0, mx0), mn1 = fmaxf(m1, mx1);
        float al0 = __expf(m0 - mn0), al1 = __expf(m1 - mn1);

        // rescale accumulators
#pragma unroll
        for (int nf = 0; nf < 8; nf++) {
            out[nf][0] *= al0; out[nf][1] *= al0;
            out[nf][2] *= al1; out[nf][3] *= al1;
        }

        // ---- exp + fp16 P fragments + P.V (single-term fp16) ----
        float sum0 = 0.f, sum1 = 0.f;
#pragma unroll
        for (int kk = 0; kk < 8; kk++) {
            uint32_t ph[4];
#pragma unroll
            for (int half = 0; half < 2; half++) {
                int nf = kk * 2 + half;
                float p0 = __expf(sacc[nf][0] - mn0);
                float p1 = __expf(sacc[nf][1] - mn0);
                float p2 = __expf(sacc[nf][2] - mn1);
                float p3 = __expf(sacc[nf][3] - mn1);
                sum0 += p0 + p1;
                sum1 += p2 + p3;
                __half2 a01 = __floats2half2_rn(p0, p1);
                __half2 a23 = __floats2half2_rn(p2, p3);
                ph[half*2]     = *(uint32_t*)&a01;
                ph[half*2 + 1] = *(uint32_t*)&a23;
            }
#pragma unroll
            for (int jp = 0; jp < 8; jp += 2) {
                uint32_t off = (uint32_t)(kk * 16 + vrow) * 128 + (jp + vcsel) * 16;
                off ^= (off >> 3) & 0x70;
                uint32_t v0, v1, v2, v3;
                LDSM4T(v0, v1, v2, v3, sVh + off);
                MMA16816F16(out[jp],   ph[0], ph[1], ph[2], ph[3], v0, v1);
                MMA16816F16(out[jp+1], ph[0], ph[1], ph[2], ph[3], v2, v3);
            }
        }
        sum0 += __shfl_xor_sync(0xffffffffu, sum0, 1);
        sum0 += __shfl_xor_sync(0xffffffffu, sum0, 2);
        sum1 += __shfl_xor_sync(0xffffffffu, sum1, 1);
        sum1 += __shfl_xor_sync(0xffffffffu, sum1, 2);
        l0 = l0 * al0 + sum0;
        l1 = l1 * al1 + sum1;
        m0 = mn0; m1 = mn1;
    }

    // ---- epilogue ----
    float inv0 = 1.f / l0, inv1 = 1.f / l1;
#pragma unroll
    for (int nf = 0; nf < 8; nf++) {
        int col = h * HDIM + nf * 8 + (lane & 3) * 2;
        size_t i0 = (size_t)(b * SEQ + r0g) * DMODEL + col;
        size_t i1 = (size_t)(b * SEQ + r1g) * DMODEL + col;
        store_split2(Oh, Ol, i0, out[nf][0] * inv0, out[nf][1] * inv0);
        store_split2(Oh, Ol, i1, out[nf][2] * inv1, out[nf][3] * inv1);
    }
}

// ---------------- launcher ---------------------------------------------------
extern "C" void kernel_launch(void* const* d_in, const int* in_sizes, int n_in,
                              void* d_out, int out_size)
{
    const float* x  = (const float*)d_in[0];
    const float* Wq = (const float*)d_in[2];
    const float* Wk = (const float*)d_in[3];
    const float* Wv = (const float*)d_in[4];
    const float* Wo = (const float*)d_in[5];
    float* out = (float*)d_out;

    float *kfb, *vfb;
    cudaGetSymbolAddress((void**)&kfb, g_kfb);
    cudaGetSymbolAddress((void**)&vfb, g_vfb);

    __nv_bfloat16 *xh, *xl, *wqh, *wql, *wkh, *wkl, *wvh, *wvl, *woh, *wol;
    __nv_bfloat16 *qh, *ql, *kh, *kl;
    __half *vhf;
    cudaGetSymbolAddress((void**)&xh, g_xh);
    cudaGetSymbolAddress((void**)&xl, g_xl);
    cudaGetSymbolAddress((void**)&wqh, g_wqh);
    cudaGetSymbolAddress((void**)&wql, g_wql);
    cudaGetSymbolAddress((void**)&wkh, g_wkh);
    cudaGetSymbolAddress((void**)&wkl, g_wkl);
    cudaGetSymbolAddress((void**)&wvh, g_wvh);
    cudaGetSymbolAddress((void**)&wvl, g_wvl);
    cudaGetSymbolAddress((void**)&woh, g_woh);
    cudaGetSymbolAddress((void**)&wol, g_wol);
    cudaGetSymbolAddress((void**)&qh, g_qh);
    cudaGetSymbolAddress((void**)&ql, g_ql);
    cudaGetSymbolAddress((void**)&kh, g_kh);
    cudaGetSymbolAddress((void**)&kl, g_kl);
    cudaGetSymbolAddress((void**)&vhf, g_vhf);

    float* kdst;
    float* vdst;
    if (out_size >= OUTN + 2 * KVN) {
        kdst = out + OUTN;
        vdst = out + OUTN + KVN;
    } else {
        kdst = kfb;
        vdst = vfb;
    }

    cudaFuncSetAttribute(mma_gemm, cudaFuncAttributeMaxDynamicSharedMemorySize, GEMM_SMEM);
    cudaFuncSetAttribute(qkv_gemm, cudaFuncAttributeMaxDynamicSharedMemorySize, GEMM_SMEM);
    cudaFuncSetAttribute(flash_mma, cudaFuncAttributeMaxDynamicSharedMemorySize, FLASH_SMEM);

    RopeTab tab;
    for (int p = 0; p < 32; p++) {
        double invf = exp(-(double)p * (log(10000.0) / 32.0));
        float hi = (float)invf;
        tab.hi[p] = hi;
        tab.lo[p] = (float)(invf - (double)hi);
    }

    // splits: x + 4 weights
    split_kernel<<<OUTN/4/256, 256>>>((const float4*)x, (__nv_bfloat162*)xh, (__nv_bfloat162*)xl, OUTN/4);
    Ptrs4 wp;
    wp.s[0] = (const float4*)Wq; wp.h[0] = (__nv_bfloat162*)wqh; wp.l[0] = (__nv_bfloat162*)wql;
    wp.s[1] = (const float4*)Wk; wp.h[1] = (__nv_bfloat162*)wkh; wp.l[1] = (__nv_bfloat162*)wkl;
    wp.s[2] = (const float4*)Wv; wp.h[2] = (__nv_bfloat162*)wvh; wp.l[2] = (__nv_bfloat162*)wvl;
    wp.s[3] = (const float4*)Wo; wp.h[3] = (__nv_bfloat162*)woh; wp.l[3] = (__nv_bfloat162*)wol;
    dim3 wgrid(WN/4/256, 4);
    wsplit<<<wgrid, 256>>>(wp, WN/4);

    // fused QKV projection + RoPE + split (128x64 tiles, 2 CTA/SM)
    dim3 ggrid(DMODEL / 64, MROWS / 128, 3);   // (16, 32, 3) = 1536 CTAs
    qkv_gemm<<<ggrid, 256, GEMM_SMEM>>>(xh, xl,
                                        wqh, wql, wkh, wkl, wvh, wvl,
                                        qh, ql, kh, kl, vhf,
                                        kdst, vdst, tab);

    // tensor-core flash attention -> split bf16 attn output
    dim3 fgrid(SEQ / 128, NHEADS, BATCH);      // (16, 16, 2)
    flash_mma<<<fgrid, 256, FLASH_SMEM>>>(qh, ql, kh, kl, vhf, xh, xl);

    // output projection (128x64 tiles, 2 CTA/SM)
    dim3 ogrid(DMODEL / 64, MROWS / 128);      // (16, 32) = 512 CTAs
    mma_gemm<<<ogrid, 256, GEMM_SMEM>>>(xh, xl, woh, wol, out);
}

// round 9
// speedup vs baseline: 1.4547x; 1.1591x over previous
#include <cuda_runtime.h>
#include <cuda_bf16.h>
#include <cuda_fp16.h>
#include <math.h>
#include <stdint.h>

// Problem constants
#define BATCH 2
#define SEQ 2048
#define DMODEL 1024
#define NHEADS 16
#define HDIM 64
#define MROWS (BATCH*SEQ)              // 4096
#define OUTN  (BATCH*SEQ*DMODEL)       // 4194304
#define KVN   (BATCH*NHEADS*SEQ*HDIM)  // 4194304
#define WN    (DMODEL*DMODEL)          // 1048576

// ---------------- scratch (device globals; no allocations allowed) ----------
__device__ float g_kfb[KVN];
__device__ float g_vfb[KVN];
__device__ __nv_bfloat16 g_xh[OUTN];
__device__ __nv_bfloat16 g_xl[OUTN];
__device__ __nv_bfloat16 g_wqh[WN], g_wql[WN];
__device__ __nv_bfloat16 g_wkh[WN], g_wkl[WN];
__device__ __nv_bfloat16 g_wvh[WN], g_wvl[WN];
__device__ __nv_bfloat16 g_woh[WN], g_wol[WN];
__device__ __half g_qhf[KVN];          // Q fp16 (pre-scaled by 0.125*log2e)
__device__ __half g_khf[KVN];          // K fp16
__device__ __half g_vhf[KVN];          // V fp16

// ====================== helpers ==============================================
__device__ __forceinline__ uint32_t smem_to_u32(const void* p) {
    uint32_t a;
    asm("{ .reg .u64 t; cvta.to.shared.u64 t, %1; cvt.u32.u64 %0, t; }"
        : "=r"(a) : "l"(p));
    return a;
}

__device__ __forceinline__ void cp16(uint32_t saddr, const void* g) {
    asm volatile("cp.async.cg.shared.global [%0], [%1], 16;"
                 :: "r"(saddr), "l"(g) : "memory");
}

__device__ __forceinline__ float ex2f(float x) {
    float y;
    asm("ex2.approx.ftz.f32 %0, %1;" : "=f"(y) : "f"(x));
    return y;
}

#define LDSM4(r0, r1, r2, r3, addr) \
    asm volatile("ldmatrix.sync.aligned.m8n8.x4.shared.b16 {%0,%1,%2,%3}, [%4];" \
                 : "=r"(r0), "=r"(r1), "=r"(r2), "=r"(r3) : "r"(addr))

#define LDSM4T(r0, r1, r2, r3, addr) \
    asm volatile("ldmatrix.sync.aligned.m8n8.x4.trans.shared.b16 {%0,%1,%2,%3}, [%4];" \
                 : "=r"(r0), "=r"(r1), "=r"(r2), "=r"(r3) : "r"(addr))

#define MMA16816(d, a0, a1, a2, a3, b0, b1) \
    asm volatile("mma.sync.aligned.m16n8k16.row.col.f32.bf16.bf16.f32 " \
                 "{%0,%1,%2,%3}, {%4,%5,%6,%7}, {%8,%9}, {%0,%1,%2,%3};" \
                 : "+f"((d)[0]), "+f"((d)[1]), "+f"((d)[2]), "+f"((d)[3]) \
                 : "r"(a0), "r"(a1), "r"(a2), "r"(a3), "r"(b0), "r"(b1))

#define MMA16816F16(d, a0, a1, a2, a3, b0, b1) \
    asm volatile("mma.sync.aligned.m16n8k16.row.col.f32.f16.f16.f32 " \
                 "{%0,%1,%2,%3}, {%4,%5,%6,%7}, {%8,%9}, {%0,%1,%2,%3};" \
                 : "+f"((d)[0]), "+f"((d)[1]), "+f"((d)[2]), "+f"((d)[3]) \
                 : "r"(a0), "r"(a1), "r"(a2), "r"(a3), "r"(b0), "r"(b1))

__device__ __forceinline__ void store_split2(__nv_bfloat16* H, __nv_bfloat16* L,
                                             size_t idx, float a, float b) {
    __nv_bfloat16 ha = __float2bfloat16(a), hb = __float2bfloat16(b);
    float ra = a - __bfloat162float(ha), rb = b - __bfloat162float(hb);
    *(__nv_bfloat162*)(H + idx) = __halves2bfloat162(ha, hb);
    *(__nv_bfloat162*)(L + idx) =
        __halves2bfloat162(__float2bfloat16(ra), __float2bfloat16(rb));
}

struct RopeTab { float hi[32]; float lo[32]; };

// ====================== bf16 split conversion ================================
__global__ void split_kernel(const float4* __restrict__ src,
                             __nv_bfloat162* __restrict__ hi,
                             __nv_bfloat162* __restrict__ lo, int n4)
{
    int i = blockIdx.x * blockDim.x + threadIdx.x;
    if (i >= n4) return;
    float4 v = src[i];
    __nv_bfloat16 h0 = __float2bfloat16(v.x);
    __nv_bfloat16 h1 = __float2bfloat16(v.y);
    __nv_bfloat16 h2 = __float2bfloat16(v.z);
    __nv_bfloat16 h3 = __float2bfloat16(v.w);
    float r0 = v.x - __bfloat162float(h0);
    float r1 = v.y - __bfloat162float(h1);
    float r2 = v.z - __bfloat162float(h2);
    float r3 = v.w - __bfloat162float(h3);
    hi[2*i]   = __halves2bfloat162(h0, h1);
    hi[2*i+1] = __halves2bfloat162(h2, h3);
    lo[2*i]   = __halves2bfloat162(__float2bfloat16(r0), __float2bfloat16(r1));
    lo[2*i+1] = __halves2bfloat162(__float2bfloat16(r2), __float2bfloat16(r3));
}

struct Ptrs4 {
    const float4* s[4];
    __nv_bfloat162* h[4];
    __nv_bfloat162* l[4];
};

__global__ void wsplit(Ptrs4 p, int n4)
{
    int i = blockIdx.x * blockDim.x + threadIdx.x;
    int w = blockIdx.y;
    if (i >= n4) return;
    float4 v = p.s[w][i];
    __nv_bfloat16 h0 = __float2bfloat16(v.x);
    __nv_bfloat16 h1 = __float2bfloat16(v.y);
    __nv_bfloat16 h2 = __float2bfloat16(v.z);
    __nv_bfloat16 h3 = __float2bfloat16(v.w);
    float r0 = v.x - __bfloat162float(h0);
    float r1 = v.y - __bfloat162float(h1);
    float r2 = v.z - __bfloat162float(h2);
    float r3 = v.w - __bfloat162float(h3);
    p.h[w][2*i]   = __halves2bfloat162(h0, h1);
    p.h[w][2*i+1] = __halves2bfloat162(h2, h3);
    p.l[w][2*i]   = __halves2bfloat162(__float2bfloat16(r0), __float2bfloat16(r1));
    p.l[w][2*i+1] = __halves2bfloat162(__float2bfloat16(r2), __float2bfloat16(r3));
}

// ====================== mma.sync split-bf16 GEMM core (128x64 tile) ==========
#define TBA 16384
#define TBB 8192
#define STAGE (2*TBA + 2*TBB)      // 49152
#define GEMM_SMEM (2*STAGE)        // 98304
#define NCK 16

__device__ __forceinline__ void stage_load(uint32_t sb,
    const uint4* __restrict__ Ah, const uint4* __restrict__ Al,
    const uint4* __restrict__ Bh, const uint4* __restrict__ Bl,
    int m0, int n0, int c, int tid)
{
    const int q = tid & 7;
    const int r0 = tid >> 3;   // 0..31
#pragma unroll
    for (int it = 0; it < 4; it++) {
        int row = r0 + it * 32;
        uint32_t off = row * 128 + q * 16;
        off ^= (off >> 3) & 0x70;
        size_t ga = (size_t)(m0 + row) * 128 + c * 8 + q;
        cp16(sb + off,        Ah + ga);
        cp16(sb + TBA + off,  Al + ga);
    }
#pragma unroll
    for (int it = 0; it < 2; it++) {
        int row = r0 + it * 32;
        uint32_t off = row * 128 + q * 16;
        off ^= (off >> 3) & 0x70;
        size_t gb = (size_t)(n0 + row) * 128 + c * 8 + q;
        cp16(sb + 2*TBA + off,        Bh + gb);
        cp16(sb + 2*TBA + TBB + off,  Bl + gb);
    }
}

__device__ __forceinline__ void gemm_mainloop(uint32_t sbase,
    const uint4* A4h, const uint4* A4l, const uint4* B4h, const uint4* B4l,
    int m0, int n0, int tid, int wm, int wn,
    int arow, int acolb, int brow, int bcolb, float acc[2][4][4])
{
#pragma unroll
    for (int i = 0; i < 2; i++)
#pragma unroll
        for (int j = 0; j < 4; j++)
#pragma unroll
            for (int r = 0; r < 4; r++) acc[i][j][r] = 0.f;

    stage_load(sbase, A4h, A4l, B4h, B4l, m0, n0, 0, tid);
    asm volatile("cp.async.commit_group;" ::: "memory");

    for (int c = 0; c < NCK; c++) {
        __syncthreads();
        if (c + 1 < NCK) {
            stage_load(sbase + (uint32_t)((c + 1) & 1) * STAGE,
                       A4h, A4l, B4h, B4l, m0, n0, c + 1, tid);
            asm volatile("cp.async.commit_group;" ::: "memory");
            asm volatile("cp.async.wait_group 1;" ::: "memory");
        } else {
            asm volatile("cp.async.wait_group 0;" ::: "memory");
        }
        __syncthreads();

        const uint32_t sb  = sbase + (uint32_t)(c & 1) * STAGE;
        const uint32_t sAh = sb;
        const uint32_t sAl = sb + TBA;
        const uint32_t sBh = sb + 2*TBA;
        const uint32_t sBl = sb + 2*TBA + TBB;

#pragma unroll
        for (int kk = 0; kk < 4; kk++) {
            uint32_t bh[4][2], bl[4][2];
#pragma unroll
            for (int nf2 = 0; nf2 < 2; nf2++) {
                uint32_t off = (uint32_t)(wn + nf2 * 16 + brow) * 128 + kk * 32 + bcolb;
                off ^= (off >> 3) & 0x70;
                LDSM4(bh[nf2*2+0][0], bh[nf2*2+0][1], bh[nf2*2+1][0], bh[nf2*2+1][1], sBh + off);
                LDSM4(bl[nf2*2+0][0], bl[nf2*2+0][1], bl[nf2*2+1][0], bl[nf2*2+1][1], sBl + off);
            }
#pragma unroll
            for (int mf = 0; mf < 2; mf++) {
                uint32_t off = (uint32_t)(wm + mf * 16 + arow) * 128 + kk * 32 + acolb;
                off ^= (off >> 3) & 0x70;
                uint32_t ah0, ah1, ah2, ah3, al0, al1, al2, al3;
                LDSM4(ah0, ah1, ah2, ah3, sAh + off);
                LDSM4(al0, al1, al2, al3, sAl + off);
#pragma unroll
                for (int nf = 0; nf < 4; nf++) {
                    MMA16816(acc[mf][nf], ah0, ah1, ah2, ah3, bh[nf][0], bh[nf][1]);
                    MMA16816(acc[mf][nf], ah0, ah1, ah2, ah3, bl[nf][0], bl[nf][1]);
                    MMA16816(acc[mf][nf], al0, al1, al2, al3, bh[nf][0], bh[nf][1]);
                }
            }
        }
    }
}

// -------- plain GEMM (output projection): C fp32 [M,N] -----------------------
__global__ void __launch_bounds__(256, 2) mma_gemm(const __nv_bfloat16* __restrict__ Ah_,
                                                   const __nv_bfloat16* __restrict__ Al_,
                                                   const __nv_bfloat16* __restrict__ Bh_,
                                                   const __nv_bfloat16* __restrict__ Bl_,
                                                   float* __restrict__ C)
{
    extern __shared__ char smem[];
    const uint32_t sbase = smem_to_u32(smem);
    const int tid = threadIdx.x;
    const int wid = tid >> 5;
    const int lane = tid & 31;
    const int m0 = blockIdx.y * 128;
    const int n0 = blockIdx.x * 64;
    const int wm = (wid & 3) * 32;
    const int wn = (wid >> 2) * 32;
    const int t  = lane >> 3;
    const int li = lane & 7;

    float acc[2][4][4];
    gemm_mainloop(sbase, (const uint4*)Ah_, (const uint4*)Al_,
                  (const uint4*)Bh_, (const uint4*)Bl_,
                  m0, n0, tid, wm, wn,
                  (t & 1) * 8 + li, (t >> 1) * 16,
                  ((t >> 1) & 1) * 8 + li, (t & 1) * 16, acc);

    const int g  = lane >> 2;
    const int tq = lane & 3;
#pragma unroll
    for (int mf = 0; mf < 2; mf++) {
#pragma unroll
        for (int nf = 0; nf < 4; nf++) {
            int rr = m0 + wm + mf * 16 + g;
            int cc = n0 + wn + nf * 8 + tq * 2;
            *(float2*)&C[(size_t)rr * DMODEL + cc]       = make_float2(acc[mf][nf][0], acc[mf][nf][1]);
            *(float2*)&C[(size_t)(rr + 8) * DMODEL + cc] = make_float2(acc[mf][nf][2], acc[mf][nf][3]);
        }
    }
}

// -------- fused QKV GEMM + RoPE + transpose + fp16 stores ---------------------
// Q pre-scaled by 0.125*log2(e) so flash softmax uses raw ex2.
#define QSCALE 0.18033688011112042f

__global__ void __launch_bounds__(256, 2) qkv_gemm(
    const __nv_bfloat16* __restrict__ xh_, const __nv_bfloat16* __restrict__ xl_,
    const __nv_bfloat16* __restrict__ wqh_, const __nv_bfloat16* __restrict__ wql_,
    const __nv_bfloat16* __restrict__ wkh_, const __nv_bfloat16* __restrict__ wkl_,
    const __nv_bfloat16* __restrict__ wvh_, const __nv_bfloat16* __restrict__ wvl_,
    __half* __restrict__ qhf, __half* __restrict__ khf, __half* __restrict__ vhf,
    float* __restrict__ kc, float* __restrict__ vc, RopeTab tab)
{
    extern __shared__ char smem[];
    const uint32_t sbase = smem_to_u32(smem);
    const int tid = threadIdx.x;
    const int wid = tid >> 5;
    const int lane = tid & 31;
    const int m0 = blockIdx.y * 128;
    const int n0 = blockIdx.x * 64;
    const int which = blockIdx.z;
    const int wm = (wid & 3) * 32;
    const int wn = (wid >> 2) * 32;
    const int t  = lane >> 3;
    const int li = lane & 7;

    const __nv_bfloat16* Bh_ = (which == 0) ? wqh_ : (which == 1) ? wkh_ : wvh_;
    const __nv_bfloat16* Bl_ = (which == 0) ? wql_ : (which == 1) ? wkl_ : wvl_;

    float acc[2][4][4];
    gemm_mainloop(sbase, (const uint4*)xh_, (const uint4*)xl_,
                  (const uint4*)Bh_, (const uint4*)Bl_,
                  m0, n0, tid, wm, wn,
                  (t & 1) * 8 + li, (t >> 1) * 16,
                  ((t >> 1) & 1) * 8 + li, (t & 1) * 16, acc);

    const int g  = lane >> 2;
    const int tq = lane & 3;
#pragma unroll
    for (int mf = 0; mf < 2; mf++) {
#pragma unroll
        for (int nf = 0; nf < 4; nf++) {
            int cc = n0 + wn + nf * 8 + tq * 2;
            int hh = cc >> 6;
            int d  = cc & 63;
            int p  = d >> 1;
            float fhi = tab.hi[p], flo = tab.lo[p];
#pragma unroll
            for (int r = 0; r < 2; r++) {
                int rr = m0 + wm + mf * 16 + g + r * 8;
                float a = acc[mf][nf][r*2], bv = acc[mf][nf][r*2+1];
                int s  = rr & (SEQ - 1);
                int bb = rr >> 11;
                size_t dst = ((size_t)(bb * NHEADS + hh) * SEQ + s) * HDIM + d;
                if (which == 2) {
                    *(float2*)(vc + dst) = make_float2(a, bv);
                    *(__half2*)(vhf + dst) = __floats2half2_rn(a, bv);
                } else {
                    float fs = (float)s;
                    float ang = fmaf(fs, flo, fs * fhi);
                    float c, sn;
                    sincosf(ang, &sn, &c);
                    float na = a * c - bv * sn;
                    float nb = a * sn + bv * c;
                    if (which == 0) {
                        *(__half2*)(qhf + dst) = __floats2half2_rn(na * QSCALE, nb * QSCALE);
                    } else {
                        *(float2*)(kc + dst) = make_float2(na, nb);
                        *(__half2*)(khf + dst) = __floats2half2_rn(na, nb);
                    }
                }
            }
        }
    }
}

// ---------------- tensor-core causal flash attention (fp16, Bc=128) ----------
// Smem: Q fp16 16KB + 2 stages x (K 16KB + V 16KB) = 80KB
#define FQ 0
#define FST 16384
#define FSTAGE 32768
#define FLASH_SMEM (FST + 2*FSTAGE)   // 81920

__device__ __forceinline__ void flash_stage(uint32_t st,
    const uint4* __restrict__ K4, const uint4* __restrict__ V4,
    int k0, int tid)
{
#pragma unroll
    for (int it = 0; it < 4; it++) {
        int idx = tid + it * 256;        // 0..1023
        int row = idx >> 3, q = idx & 7;
        uint32_t off = row * 128 + q * 16;
        off ^= (off >> 3) & 0x70;
        size_t g = (size_t)(k0 + row) * 8 + q;
        cp16(st + off,           K4 + g);
        cp16(st + 16384 + off,   V4 + g);
    }
}

__global__ void __launch_bounds__(256, 1) flash_mma(
    const __half* __restrict__ qhf_, const __half* __restrict__ khf_,
    const __half* __restrict__ vhf_,
    __nv_bfloat16* __restrict__ Oh, __nv_bfloat16* __restrict__ Ol)
{
    extern __shared__ char smem[];
    const uint32_t sb = smem_to_u32(smem);
    const int tid = threadIdx.x;
    const int wid = tid >> 5;
    const int lane = tid & 31;
    const int qt = gridDim.x - 1 - blockIdx.x;   // heavy first
    const int h  = blockIdx.y;
    const int b  = blockIdx.z;
    const int q0 = qt * 128;
    const size_t head = (size_t)(b * NHEADS + h) * SEQ;

    const uint4* Q4 = (const uint4*)qhf_ + (head + q0) * 8;
    const uint4* K4 = (const uint4*)khf_ + head * 8;
    const uint4* V4 = (const uint4*)vhf_ + head * 8;

    const int t  = lane >> 3;
    const int li = lane & 7;
    const int arow  = (t & 1) * 8 + li;
    const int acolb = (t >> 1) * 16;
    const int brow  = ((t >> 1) & 1) * 8 + li;
    const int bcolb = (t & 1) * 16;
    const int vrow  = (t & 1) * 8 + li;
    const int vcsel = (t >> 1);

    // Q tile (single fp16)
#pragma unroll
    for (int it = 0; it < 4; it++) {
        int idx = tid + it * 256;
        int row = idx >> 3, q = idx & 7;
        uint32_t off = row * 128 + q * 16;
        off ^= (off >> 3) & 0x70;
        cp16(sb + FQ + off, Q4 + (size_t)row * 8 + q);
    }
    flash_stage(sb + FST, K4, V4, 0, tid);
    asm volatile("cp.async.commit_group;" ::: "memory");

    const int nkt = qt + 1;

    uint32_t qA[4][4];
    float out[8][4];
#pragma unroll
    for (int nf = 0; nf < 8; nf++)
#pragma unroll
        for (int r = 0; r < 4; r++) out[nf][r] = 0.f;

    float m0 = -1e30f, m1 = -1e30f, l0 = 0.f, l1 = 0.f;
    const int r0g = q0 + wid * 16 + (lane >> 2);
    const int r1g = r0g + 8;

    for (int kt = 0; kt < nkt; kt++) {
        __syncthreads();
        if (kt + 1 < nkt) {
            flash_stage(sb + FST + (uint32_t)((kt + 1) & 1) * FSTAGE,
                        K4, V4, (kt + 1) * 128, tid);
            asm volatile("cp.async.commit_group;" ::: "memory");
            asm volatile("cp.async.wait_group 1;" ::: "memory");
        } else {
            asm volatile("cp.async.wait_group 0;" ::: "memory");
        }
        __syncthreads();

        if (kt == 0) {
#pragma unroll
            for (int kk = 0; kk < 4; kk++) {
                uint32_t off = (uint32_t)(wid * 16 + arow) * 128 + kk * 32 + acolb;
                off ^= (off >> 3) & 0x70;
                LDSM4(qA[kk][0], qA[kk][1], qA[kk][2], qA[kk][3], sb + FQ + off);
            }
        }

        const uint32_t st = sb + FST + (uint32_t)(kt & 1) * FSTAGE;
        const uint32_t sK = st, sV = st + 16384;

        // ---- S' = (Q*qscale) K^T, already in log2 domain ----
        float sacc[16][4];
#pragma unroll
        for (int nf = 0; nf < 16; nf++)
#pragma unroll
            for (int r = 0; r < 4; r++) sacc[nf][r] = 0.f;

#pragma unroll
        for (int kk = 0; kk < 4; kk++) {
#pragma unroll
            for (int nfp = 0; nfp < 8; nfp++) {
                uint32_t off = (uint32_t)(nfp * 16 + brow) * 128 + kk * 32 + bcolb;
                off ^= (off >> 3) & 0x70;
                uint32_t b0, b1, b2, b3;
                LDSM4(b0, b1, b2, b3, sK + off);
                MMA16816F16(sacc[nfp*2],   qA[kk][0], qA[kk][1], qA[kk][2], qA[kk][3], b0, b1);
                MMA16816F16(sacc[nfp*2+1], qA[kk][0], qA[kk][1], qA[kk][2], qA[kk][3], b2, b3);
            }
        }

        // ---- causal mask + row max (log2 domain) ----
        const bool domask = (kt == nkt - 1);
        float mx0 = -1e30f, mx1 = -1e30f;
#pragma unroll
        for (int nf = 0; nf < 16; nf++) {
            int key = kt * 128 + nf * 8 + (lane & 3) * 2;
            float s0 = sacc[nf][0];
            float s1 = sacc[nf][1];
            float s2 = sacc[nf][2];
            float s3 = sacc[nf][3];
            if (domask) {
                if (key     > r0g) s0 = -1e30f;
                if (key + 1 > r0g) s1 = -1e30f;
                if (key     > r1g) s2 = -1e30f;
                if (key + 1 > r1g) s3 = -1e30f;
            }
            sacc[nf][0] = s0; sacc[nf][1] = s1; sacc[nf][2] = s2; sacc[nf][3] = s3;
            mx0 = fmaxf(mx0, fmaxf(s0, s1));
            mx1 = fmaxf(mx1, fmaxf(s2, s3));
        }
        mx0 = fmaxf(mx0, __shfl_xor_sync(0xffffffffu, mx0, 1));
        mx0 = fmaxf(mx0, __shfl_xor_sync(0xffffffffu, mx0, 2));
        mx1 = fmaxf(mx1, __shfl_xor_sync(0xffffffffu, mx1, 1));
        mx1 = fmaxf(mx1, __shfl_xor_sync(0xffffffffu, mx1, 2));

        float mn0 = fmaxf(m0, mx0), mn1 = fmaxf(m1, mx1);
        float al0 = ex2f(m0 - mn0), al1 = ex2f(m1 - mn1);

        // rescale accumulators
#pragma unroll
        for (int nf = 0; nf < 8; nf++) {
            out[nf][0] *= al0; out[nf][1] *= al0;
            out[nf][2] *= al1; out[nf][3] *= al1;
        }

        // ---- exp2 + fp16 P fragments + P.V ----
        float sum0 = 0.f, sum1 = 0.f;
#pragma unroll
        for (int kk = 0; kk < 8; kk++) {
            uint32_t ph[4];
#pragma unroll
            for (int half = 0; half < 2; half++) {
                int nf = kk * 2 + half;
                float p0 = ex2f(sacc[nf][0] - mn0);
                float p1 = ex2f(sacc[nf][1] - mn0);
                float p2 = ex2f(sacc[nf][2] - mn1);
                float p3 = ex2f(sacc[nf][3] - mn1);
                sum0 += p0 + p1;
                sum1 += p2 + p3;
                __half2 a01 = __floats2half2_rn(p0, p1);
                __half2 a23 = __floats2half2_rn(p2, p3);
                ph[half*2]     = *(uint32_t*)&a01;
                ph[half*2 + 1] = *(uint32_t*)&a23;
            }
#pragma unroll
            for (int jp = 0; jp < 8; jp += 2) {
                uint32_t off = (uint32_t)(kk * 16 + vrow) * 128 + (jp + vcsel) * 16;
                off ^= (off >> 3) & 0x70;
                uint32_t v0, v1, v2, v3;
                LDSM4T(v0, v1, v2, v3, sV + off);
                MMA16816F16(out[jp],   ph[0], ph[1], ph[2], ph[3], v0, v1);
                MMA16816F16(out[jp+1], ph[0], ph[1], ph[2], ph[3], v2, v3);
            }
        }
        sum0 += __shfl_xor_sync(0xffffffffu, sum0, 1);
        sum0 += __shfl_xor_sync(0xffffffffu, sum0, 2);
        sum1 += __shfl_xor_sync(0xffffffffu, sum1, 1);
        sum1 += __shfl_xor_sync(0xffffffffu, sum1, 2);
        l0 = l0 * al0 + sum0;
        l1 = l1 * al1 + sum1;
        m0 = mn0; m1 = mn1;
    }

    // ---- epilogue ----
    float inv0 = 1.f / l0, inv1 = 1.f / l1;
#pragma unroll
    for (int nf = 0; nf < 8; nf++) {
        int col = h * HDIM + nf * 8 + (lane & 3) * 2;
        size_t i0 = (size_t)(b * SEQ + r0g) * DMODEL + col;
        size_t i1 = (size_t)(b * SEQ + r1g) * DMODEL + col;
        store_split2(Oh, Ol, i0, out[nf][0] * inv0, out[nf][1] * inv0);
        store_split2(Oh, Ol, i1, out[nf][2] * inv1, out[nf][3] * inv1);
    }
}

// ---------------- launcher ---------------------------------------------------
extern "C" void kernel_launch(void* const* d_in, const int* in_sizes, int n_in,
                              void* d_out, int out_size)
{
    const float* x  = (const float*)d_in[0];
    const float* Wq = (const float*)d_in[2];
    const float* Wk = (const float*)d_in[3];
    const float* Wv = (const float*)d_in[4];
    const float* Wo = (const float*)d_in[5];
    float* out = (float*)d_out;

    float *kfb, *vfb;
    cudaGetSymbolAddress((void**)&kfb, g_kfb);
    cudaGetSymbolAddress((void**)&vfb, g_vfb);

    __nv_bfloat16 *xh, *xl, *wqh, *wql, *wkh, *wkl, *wvh, *wvl, *woh, *wol;
    __half *qhf, *khf, *vhf;
    cudaGetSymbolAddress((void**)&xh, g_xh);
    cudaGetSymbolAddress((void**)&xl, g_xl);
    cudaGetSymbolAddress((void**)&wqh, g_wqh);
    cudaGetSymbolAddress((void**)&wql, g_wql);
    cudaGetSymbolAddress((void**)&wkh, g_wkh);
    cudaGetSymbolAddress((void**)&wkl, g_wkl);
    cudaGetSymbolAddress((void**)&wvh, g_wvh);
    cudaGetSymbolAddress((void**)&wvl, g_wvl);
    cudaGetSymbolAddress((void**)&woh, g_woh);
    cudaGetSymbolAddress((void**)&wol, g_wol);
    cudaGetSymbolAddress((void**)&qhf, g_qhf);
    cudaGetSymbolAddress((void**)&khf, g_khf);
    cudaGetSymbolAddress((void**)&vhf, g_vhf);

    float* kdst;
    float* vdst;
    if (out_size >= OUTN + 2 * KVN) {
        kdst = out + OUTN;
        vdst = out + OUTN + KVN;
    } else {
        kdst = kfb;
        vdst = vfb;
    }

    cudaFuncSetAttribute(mma_gemm, cudaFuncAttributeMaxDynamicSharedMemorySize, GEMM_SMEM);
    cudaFuncSetAttribute(qkv_gemm, cudaFuncAttributeMaxDynamicSharedMemorySize, GEMM_SMEM);
    cudaFuncSetAttribute(flash_mma, cudaFuncAttributeMaxDynamicSharedMemorySize, FLASH_SMEM);

    RopeTab tab;
    for (int p = 0; p < 32; p++) {
        double invf = exp(-(double)p * (log(10000.0) / 32.0));
        float hi = (float)invf;
        tab.hi[p] = hi;
        tab.lo[p] = (float)(invf - (double)hi);
    }

    // splits: x + 4 weights
    split_kernel<<<OUTN/4/256, 256>>>((const float4*)x, (__nv_bfloat162*)xh, (__nv_bfloat162*)xl, OUTN/4);
    Ptrs4 wp;
    wp.s[0] = (const float4*)Wq; wp.h[0] = (__nv_bfloat162*)wqh; wp.l[0] = (__nv_bfloat162*)wql;
    wp.s[1] = (const float4*)Wk; wp.h[1] = (__nv_bfloat162*)wkh; wp.l[1] = (__nv_bfloat162*)wkl;
    wp.s[2] = (const float4*)Wv; wp.h[2] = (__nv_bfloat162*)wvh; wp.l[2] = (__nv_bfloat162*)wvl;
    wp.s[3] = (const float4*)Wo; wp.h[3] = (__nv_bfloat162*)woh; wp.l[3] = (__nv_bfloat162*)wol;
    dim3 wgrid(WN/4/256, 4);
    wsplit<<<wgrid, 256>>>(wp, WN/4);

    // fused QKV projection + RoPE + fp16 stores (128x64 tiles, 2 CTA/SM)
    dim3 ggrid(DMODEL / 64, MROWS / 128, 3);   // (16, 32, 3) = 1536 CTAs
    qkv_gemm<<<ggrid, 256, GEMM_SMEM>>>(xh, xl,
                                        wqh, wql, wkh, wkl, wvh, wvl,
                                        qhf, khf, vhf,
                                        kdst, vdst, tab);

    // tensor-core flash attention (all fp16) -> split bf16 attn output
    dim3 fgrid(SEQ / 128, NHEADS, BATCH);      // (16, 16, 2)
    flash_mma<<<fgrid, 256, FLASH_SMEM>>>(qhf, khf, vhf, xh, xl);

    // output projection (128x64 tiles, 2 CTA/SM)
    dim3 ogrid(DMODEL / 64, MROWS / 128);      // (16, 32) = 512 CTAs
    mma_gemm<<<ogrid, 256, GEMM_SMEM>>>(xh, xl, woh, wol, out);
}

// round 10
// speedup vs baseline: 1.8255x; 1.2549x over previous
#include <cuda_runtime.h>
#include <cuda_bf16.h>
#include <cuda_fp16.h>
#include <math.h>
#include <stdint.h>

// Problem constants
#define BATCH 2
#define SEQ 2048
#define DMODEL 1024
#define NHEADS 16
#define HDIM 64
#define MROWS (BATCH*SEQ)              // 4096
#define OUTN  (BATCH*SEQ*DMODEL)       // 4194304
#define KVN   (BATCH*NHEADS*SEQ*HDIM)  // 4194304
#define WN    (DMODEL*DMODEL)          // 1048576

// ---------------- scratch (device globals; no allocations allowed) ----------
__device__ float g_kfb[KVN];
__device__ float g_vfb[KVN];
__device__ __half g_xh[OUTN];          // activation hi (x, then attn-out)
__device__ __half g_xl[OUTN];          // activation lo residual
__device__ __half g_wq[WN], g_wk[WN], g_wv[WN], g_wo[WN];   // weights fp16
__device__ __half g_qhf[KVN];          // Q fp16 (pre-scaled by 0.125*log2e)
__device__ __half g_khf[KVN];          // K fp16
__device__ __half g_vhf[KVN];          // V fp16

// ====================== helpers ==============================================
__device__ __forceinline__ uint32_t smem_to_u32(const void* p) {
    uint32_t a;
    asm("{ .reg .u64 t; cvta.to.shared.u64 t, %1; cvt.u32.u64 %0, t; }"
        : "=r"(a) : "l"(p));
    return a;
}

__device__ __forceinline__ void cp16(uint32_t saddr, const void* g) {
    asm volatile("cp.async.cg.shared.global [%0], [%1], 16;"
                 :: "r"(saddr), "l"(g) : "memory");
}

__device__ __forceinline__ float ex2f(float x) {
    float y;
    asm("ex2.approx.ftz.f32 %0, %1;" : "=f"(y) : "f"(x));
    return y;
}

#define LDSM4(r0, r1, r2, r3, addr) \
    asm volatile("ldmatrix.sync.aligned.m8n8.x4.shared.b16 {%0,%1,%2,%3}, [%4];" \
                 : "=r"(r0), "=r"(r1), "=r"(r2), "=r"(r3) : "r"(addr))

#define LDSM4T(r0, r1, r2, r3, addr) \
    asm volatile("ldmatrix.sync.aligned.m8n8.x4.trans.shared.b16 {%0,%1,%2,%3}, [%4];" \
                 : "=r"(r0), "=r"(r1), "=r"(r2), "=r"(r3) : "r"(addr))

#define MMA16816F16(d, a0, a1, a2, a3, b0, b1) \
    asm volatile("mma.sync.aligned.m16n8k16.row.col.f32.f16.f16.f32 " \
                 "{%0,%1,%2,%3}, {%4,%5,%6,%7}, {%8,%9}, {%0,%1,%2,%3};" \
                 : "+f"((d)[0]), "+f"((d)[1]), "+f"((d)[2]), "+f"((d)[3]) \
                 : "r"(a0), "r"(a1), "r"(a2), "r"(a3), "r"(b0), "r"(b1))

// fp16 hi/lo split store (activations; combined ~22 mantissa bits)
__device__ __forceinline__ void store_split2h(__half* H, __half* L,
                                              size_t idx, float a, float b) {
    __half ha = __float2half_rn(a), hb = __float2half_rn(b);
    float ra = a - __half2float(ha), rb = b - __half2float(hb);
    *(__half2*)(H + idx) = __halves2half2(ha, hb);
    *(__half2*)(L + idx) = __floats2half2_rn(ra, rb);
}

struct RopeTab { float hi[32]; float lo[32]; };

// ====================== conversions ==========================================
// x (fp32) -> fp16 hi + fp16 residual
__global__ void xsplit_kernel(const float4* __restrict__ src,
                              __half2* __restrict__ hi,
                              __half2* __restrict__ lo, int n4)
{
    int i = blockIdx.x * blockDim.x + threadIdx.x;
    if (i >= n4) return;
    float4 v = src[i];
    __half h0 = __float2half_rn(v.x), h1 = __float2half_rn(v.y);
    __half h2 = __float2half_rn(v.z), h3 = __float2half_rn(v.w);
    float r0 = v.x - __half2float(h0);
    float r1 = v.y - __half2float(h1);
    float r2 = v.z - __half2float(h2);
    float r3 = v.w - __half2float(h3);
    hi[2*i]   = __halves2half2(h0, h1);
    hi[2*i+1] = __halves2half2(h2, h3);
    lo[2*i]   = __floats2half2_rn(r0, r1);
    lo[2*i+1] = __floats2half2_rn(r2, r3);
}

// weights (fp32) -> single fp16, 4 at once
struct WPtrs {
    const float4* s[4];
    __half2* d[4];
};

__global__ void wconv(WPtrs p, int n4)
{
    int i = blockIdx.x * blockDim.x + threadIdx.x;
    int w = blockIdx.y;
    if (i >= n4) return;
    float4 v = p.s[w][i];
    p.d[w][2*i]   = __floats2half2_rn(v.x, v.y);
    p.d[w][2*i+1] = __floats2half2_rn(v.z, v.w);
}

// ====================== asymmetric fp16 GEMM core (128x64 tile) ==============
// C = (Ah + Al) * B^T, Ah/Al fp16 split activations, B fp16 weights. 2 MMA/step.
// Stage: Ah(16K) + Al(16K) + B(8K) = 40KB; x2 = 80KB -> 2 CTA/SM
#define TBA 16384
#define TBB 8192
#define STAGE (2*TBA + TBB)        // 40960
#define GEMM_SMEM (2*STAGE)        // 81920
#define NCK 16

__device__ __forceinline__ void stage_load(uint32_t sb,
    const uint4* __restrict__ Ah, const uint4* __restrict__ Al,
    const uint4* __restrict__ B4,
    int m0, int n0, int c, int tid)
{
    const int q = tid & 7;
    const int r0 = tid >> 3;   // 0..31
#pragma unroll
    for (int it = 0; it < 4; it++) {
        int row = r0 + it * 32;
        uint32_t off = row * 128 + q * 16;
        off ^= (off >> 3) & 0x70;
        size_t ga = (size_t)(m0 + row) * 128 + c * 8 + q;
        cp16(sb + off,        Ah + ga);
        cp16(sb + TBA + off,  Al + ga);
    }
#pragma unroll
    for (int it = 0; it < 2; it++) {
        int row = r0 + it * 32;
        uint32_t off = row * 128 + q * 16;
        off ^= (off >> 3) & 0x70;
        size_t gb = (size_t)(n0 + row) * 128 + c * 8 + q;
        cp16(sb + 2*TBA + off, B4 + gb);
    }
}

// warp layout: wm=(wid&3)*32, wn=(wid>>2)*32; warp tile 32x32
__device__ __forceinline__ void gemm_mainloop(uint32_t sbase,
    const uint4* A4h, const uint4* A4l, const uint4* B4,
    int m0, int n0, int tid, int wm, int wn,
    int arow, int acolb, int brow, int bcolb, float acc[2][4][4])
{
#pragma unroll
    for (int i = 0; i < 2; i++)
#pragma unroll
        for (int j = 0; j < 4; j++)
#pragma unroll
            for (int r = 0; r < 4; r++) acc[i][j][r] = 0.f;

    stage_load(sbase, A4h, A4l, B4, m0, n0, 0, tid);
    asm volatile("cp.async.commit_group;" ::: "memory");

    for (int c = 0; c < NCK; c++) {
        __syncthreads();
        if (c + 1 < NCK) {
            stage_load(sbase + (uint32_t)((c + 1) & 1) * STAGE,
                       A4h, A4l, B4, m0, n0, c + 1, tid);
            asm volatile("cp.async.commit_group;" ::: "memory");
            asm volatile("cp.async.wait_group 1;" ::: "memory");
        } else {
            asm volatile("cp.async.wait_group 0;" ::: "memory");
        }
        __syncthreads();

        const uint32_t sb  = sbase + (uint32_t)(c & 1) * STAGE;
        const uint32_t sAh = sb;
        const uint32_t sAl = sb + TBA;
        const uint32_t sB  = sb + 2*TBA;

#pragma unroll
        for (int kk = 0; kk < 4; kk++) {
            uint32_t bb[4][2];
#pragma unroll
            for (int nf2 = 0; nf2 < 2; nf2++) {
                uint32_t off = (uint32_t)(wn + nf2 * 16 + brow) * 128 + kk * 32 + bcolb;
                off ^= (off >> 3) & 0x70;
                LDSM4(bb[nf2*2+0][0], bb[nf2*2+0][1], bb[nf2*2+1][0], bb[nf2*2+1][1], sB + off);
            }
#pragma unroll
            for (int mf = 0; mf < 2; mf++) {
                uint32_t off = (uint32_t)(wm + mf * 16 + arow) * 128 + kk * 32 + acolb;
                off ^= (off >> 3) & 0x70;
                uint32_t ah0, ah1, ah2, ah3, al0, al1, al2, al3;
                LDSM4(ah0, ah1, ah2, ah3, sAh + off);
                LDSM4(al0, al1, al2, al3, sAl + off);
#pragma unroll
                for (int nf = 0; nf < 4; nf++) {
                    MMA16816F16(acc[mf][nf], ah0, ah1, ah2, ah3, bb[nf][0], bb[nf][1]);
                    MMA16816F16(acc[mf][nf], al0, al1, al2, al3, bb[nf][0], bb[nf][1]);
                }
            }
        }
    }
}

// -------- plain GEMM (output projection): C fp32 [M,N] -----------------------
__global__ void __launch_bounds__(256, 2) mma_gemm(const __half* __restrict__ Ah_,
                                                   const __half* __restrict__ Al_,
                                                   const __half* __restrict__ B_,
                                                   float* __restrict__ C)
{
    extern __shared__ char smem[];
    const uint32_t sbase = smem_to_u32(smem);
    const int tid = threadIdx.x;
    const int wid = tid >> 5;
    const int lane = tid & 31;
    const int m0 = blockIdx.y * 128;
    const int n0 = blockIdx.x * 64;
    const int wm = (wid & 3) * 32;
    const int wn = (wid >> 2) * 32;
    const int t  = lane >> 3;
    const int li = lane & 7;

    float acc[2][4][4];
    gemm_mainloop(sbase, (const uint4*)Ah_, (const uint4*)Al_, (const uint4*)B_,
                  m0, n0, tid, wm, wn,
                  (t & 1) * 8 + li, (t >> 1) * 16,
                  ((t >> 1) & 1) * 8 + li, (t & 1) * 16, acc);

    const int g  = lane >> 2;
    const int tq = lane & 3;
#pragma unroll
    for (int mf = 0; mf < 2; mf++) {
#pragma unroll
        for (int nf = 0; nf < 4; nf++) {
            int rr = m0 + wm + mf * 16 + g;
            int cc = n0 + wn + nf * 8 + tq * 2;
            *(float2*)&C[(size_t)rr * DMODEL + cc]       = make_float2(acc[mf][nf][0], acc[mf][nf][1]);
            *(float2*)&C[(size_t)(rr + 8) * DMODEL + cc] = make_float2(acc[mf][nf][2], acc[mf][nf][3]);
        }
    }
}

// -------- fused QKV GEMM + RoPE + transpose + fp16 stores ---------------------
// Q pre-scaled by 0.125*log2(e) so flash softmax uses raw ex2.
#define QSCALE 0.18033688011112042f

__global__ void __launch_bounds__(256, 2) qkv_gemm(
    const __half* __restrict__ xh_, const __half* __restrict__ xl_,
    const __half* __restrict__ wq_, const __half* __restrict__ wk_,
    const __half* __restrict__ wv_,
    __half* __restrict__ qhf, __half* __restrict__ khf, __half* __restrict__ vhf,
    float* __restrict__ kc, float* __restrict__ vc, RopeTab tab)
{
    extern __shared__ char smem[];
    const uint32_t sbase = smem_to_u32(smem);
    const int tid = threadIdx.x;
    const int wid = tid >> 5;
    const int lane = tid & 31;
    const int m0 = blockIdx.y * 128;
    const int n0 = blockIdx.x * 64;
    const int which = blockIdx.z;
    const int wm = (wid & 3) * 32;
    const int wn = (wid >> 2) * 32;
    const int t  = lane >> 3;
    const int li = lane & 7;

    const __half* B_ = (which == 0) ? wq_ : (which == 1) ? wk_ : wv_;

    float acc[2][4][4];
    gemm_mainloop(sbase, (const uint4*)xh_, (const uint4*)xl_, (const uint4*)B_,
                  m0, n0, tid, wm, wn,
                  (t & 1) * 8 + li, (t >> 1) * 16,
                  ((t >> 1) & 1) * 8 + li, (t & 1) * 16, acc);

    const int g  = lane >> 2;
    const int tq = lane & 3;
#pragma unroll
    for (int mf = 0; mf < 2; mf++) {
#pragma unroll
        for (int nf = 0; nf < 4; nf++) {
            int cc = n0 + wn + nf * 8 + tq * 2;
            int hh = cc >> 6;
            int d  = cc & 63;
            int p  = d >> 1;
            float fhi = tab.hi[p], flo = tab.lo[p];
#pragma unroll
            for (int r = 0; r < 2; r++) {
                int rr = m0 + wm + mf * 16 + g + r * 8;
                float a = acc[mf][nf][r*2], bv = acc[mf][nf][r*2+1];
                int s  = rr & (SEQ - 1);
                int bb = rr >> 11;
                size_t dst = ((size_t)(bb * NHEADS + hh) * SEQ + s) * HDIM + d;
                if (which == 2) {
                    *(float2*)(vc + dst) = make_float2(a, bv);
                    *(__half2*)(vhf + dst) = __floats2half2_rn(a, bv);
                } else {
                    float fs = (float)s;
                    float ang = fmaf(fs, flo, fs * fhi);
                    float c, sn;
                    sincosf(ang, &sn, &c);
                    float na = a * c - bv * sn;
                    float nb = a * sn + bv * c;
                    if (which == 0) {
                        *(__half2*)(qhf + dst) = __floats2half2_rn(na * QSCALE, nb * QSCALE);
                    } else {
                        *(float2*)(kc + dst) = make_float2(na, nb);
                        *(__half2*)(khf + dst) = __floats2half2_rn(na, nb);
                    }
                }
            }
        }
    }
}

// ---------------- tensor-core causal flash attention (fp16, Bc=128) ----------
// Smem: Q fp16 16KB + 2 stages x (K 16KB + V 16KB) = 80KB
#define FQ 0
#define FST 16384
#define FSTAGE 32768
#define FLASH_SMEM (FST + 2*FSTAGE)   // 81920

__device__ __forceinline__ void flash_stage(uint32_t st,
    const uint4* __restrict__ K4, const uint4* __restrict__ V4,
    int k0, int tid)
{
#pragma unroll
    for (int it = 0; it < 4; it++) {
        int idx = tid + it * 256;        // 0..1023
        int row = idx >> 3, q = idx & 7;
        uint32_t off = row * 128 + q * 16;
        off ^= (off >> 3) & 0x70;
        size_t g = (size_t)(k0 + row) * 8 + q;
        cp16(st + off,           K4 + g);
        cp16(st + 16384 + off,   V4 + g);
    }
}

__global__ void __launch_bounds__(256, 1) flash_mma(
    const __half* __restrict__ qhf_, const __half* __restrict__ khf_,
    const __half* __restrict__ vhf_,
    __half* __restrict__ Oh, __half* __restrict__ Ol)
{
    extern __shared__ char smem[];
    const uint32_t sb = smem_to_u32(smem);
    const int tid = threadIdx.x;
    const int wid = tid >> 5;
    const int lane = tid & 31;
    const int qt = gridDim.x - 1 - blockIdx.x;   // heavy first
    const int h  = blockIdx.y;
    const int b  = blockIdx.z;
    const int q0 = qt * 128;
    const size_t head = (size_t)(b * NHEADS + h) * SEQ;

    const uint4* Q4 = (const uint4*)qhf_ + (head + q0) * 8;
    const uint4* K4 = (const uint4*)khf_ + head * 8;
    const uint4* V4 = (const uint4*)vhf_ + head * 8;

    const int t  = lane >> 3;
    const int li = lane & 7;
    const int arow  = (t & 1) * 8 + li;
    const int acolb = (t >> 1) * 16;
    const int brow  = ((t >> 1) & 1) * 8 + li;
    const int bcolb = (t & 1) * 16;
    const int vrow  = (t & 1) * 8 + li;
    const int vcsel = (t >> 1);

    // Q tile (single fp16)
#pragma unroll
    for (int it = 0; it < 4; it++) {
        int idx = tid + it * 256;
        int row = idx >> 3, q = idx & 7;
        uint32_t off = row * 128 + q * 16;
        off ^= (off >> 3) & 0x70;
        cp16(sb + FQ + off, Q4 + (size_t)row * 8 + q);
    }
    flash_stage(sb + FST, K4, V4, 0, tid);
    asm volatile("cp.async.commit_group;" ::: "memory");

    const int nkt = qt + 1;

    uint32_t qA[4][4];
    float out[8][4];
#pragma unroll
    for (int nf = 0; nf < 8; nf++)
#pragma unroll
        for (int r = 0; r < 4; r++) out[nf][r] = 0.f;

    float m0 = -1e30f, m1 = -1e30f, l0 = 0.f, l1 = 0.f;
    const int r0g = q0 + wid * 16 + (lane >> 2);
    const int r1g = r0g + 8;

    for (int kt = 0; kt < nkt; kt++) {
        __syncthreads();
        if (kt + 1 < nkt) {
            flash_stage(sb + FST + (uint32_t)((kt + 1) & 1) * FSTAGE,
                        K4, V4, (kt + 1) * 128, tid);
            asm volatile("cp.async.commit_group;" ::: "memory");
            asm volatile("cp.async.wait_group 1;" ::: "memory");
        } else {
            asm volatile("cp.async.wait_group 0;" ::: "memory");
        }
        __syncthreads();

        if (kt == 0) {
#pragma unroll
            for (int kk = 0; kk < 4; kk++) {
                uint32_t off = (uint32_t)(wid * 16 + arow) * 128 + kk * 32 + acolb;
                off ^= (off >> 3) & 0x70;
                LDSM4(qA[kk][0], qA[kk][1], qA[kk][2], qA[kk][3], sb + FQ + off);
            }
        }

        const uint32_t st = sb + FST + (uint32_t)(kt & 1) * FSTAGE;
        const uint32_t sK = st, sV = st + 16384;

        // ---- S' = (Q*qscale) K^T, log2 domain ----
        float sacc[16][4];
#pragma unroll
        for (int nf = 0; nf < 16; nf++)
#pragma unroll
            for (int r = 0; r < 4; r++) sacc[nf][r] = 0.f;

#pragma unroll
        for (int kk = 0; kk < 4; kk++) {
#pragma unroll
            for (int nfp = 0; nfp < 8; nfp++) {
                uint32_t off = (uint32_t)(nfp * 16 + brow) * 128 + kk * 32 + bcolb;
                off ^= (off >> 3) & 0x70;
                uint32_t b0, b1, b2, b3;
                LDSM4(b0, b1, b2, b3, sK + off);
                MMA16816F16(sacc[nfp*2],   qA[kk][0], qA[kk][1], qA[kk][2], qA[kk][3], b0, b1);
                MMA16816F16(sacc[nfp*2+1], qA[kk][0], qA[kk][1], qA[kk][2], qA[kk][3], b2, b3);
            }
        }

        // ---- causal mask + row max ----
        const bool domask = (kt == nkt - 1);
        float mx0 = -1e30f, mx1 = -1e30f;
#pragma unroll
        for (int nf = 0; nf < 16; nf++) {
            int key = kt * 128 + nf * 8 + (lane & 3) * 2;
            float s0 = sacc[nf][0];
            float s1 = sacc[nf][1];
            float s2 = sacc[nf][2];
            float s3 = sacc[nf][3];
            if (domask) {
                if (key     > r0g) s0 = -1e30f;
                if (key + 1 > r0g) s1 = -1e30f;
                if (key     > r1g) s2 = -1e30f;
                if (key + 1 > r1g) s3 = -1e30f;
            }
            sacc[nf][0] = s0; sacc[nf][1] = s1; sacc[nf][2] = s2; sacc[nf][3] = s3;
            mx0 = fmaxf(mx0, fmaxf(s0, s1));
            mx1 = fmaxf(mx1, fmaxf(s2, s3));
        }
        mx0 = fmaxf(mx0, __shfl_xor_sync(0xffffffffu, mx0, 1));
        mx0 = fmaxf(mx0, __shfl_xor_sync(0xffffffffu, mx0, 2));
        mx1 = fmaxf(mx1, __shfl_xor_sync(0xffffffffu, mx1, 1));
        mx1 = fmaxf(mx1, __shfl_xor_sync(0xffffffffu, mx1, 2));

        float mn0 = fmaxf(m0, mx0), mn1 = fmaxf(m1, mx1);
        float al0 = ex2f(m0 - mn0), al1 = ex2f(m1 - mn1);

#pragma unroll
        for (int nf = 0; nf < 8; nf++) {
            out[nf][0] *= al0; out[nf][1] *= al0;
            out[nf][2] *= al1; out[nf][3] *= al1;
        }

        // ---- exp2 + fp16 P fragments + P.V ----
        float sum0 = 0.f, sum1 = 0.f;
#pragma unroll
        for (int kk = 0; kk < 8; kk++) {
            uint32_t ph[4];
#pragma unroll
            for (int half = 0; half < 2; half++) {
                int nf = kk * 2 + half;
                float p0 = ex2f(sacc[nf][0] - mn0);
                float p1 = ex2f(sacc[nf][1] - mn0);
                float p2 = ex2f(sacc[nf][2] - mn1);
                float p3 = ex2f(sacc[nf][3] - mn1);
                sum0 += p0 + p1;
                sum1 += p2 + p3;
                __half2 a01 = __floats2half2_rn(p0, p1);
                __half2 a23 = __floats2half2_rn(p2, p3);
                ph[half*2]     = *(uint32_t*)&a01;
                ph[half*2 + 1] = *(uint32_t*)&a23;
            }
#pragma unroll
            for (int jp = 0; jp < 8; jp += 2) {
                uint32_t off = (uint32_t)(kk * 16 + vrow) * 128 + (jp + vcsel) * 16;
                off ^= (off >> 3) & 0x70;
                uint32_t v0, v1, v2, v3;
                LDSM4T(v0, v1, v2, v3, sV + off);
                MMA16816F16(out[jp],   ph[0], ph[1], ph[2], ph[3], v0, v1);
                MMA16816F16(out[jp+1], ph[0], ph[1], ph[2], ph[3], v2, v3);
            }
        }
        sum0 += __shfl_xor_sync(0xffffffffu, sum0, 1);
        sum0 += __shfl_xor_sync(0xffffffffu, sum0, 2);
        sum1 += __shfl_xor_sync(0xffffffffu, sum1, 1);
        sum1 += __shfl_xor_sync(0xffffffffu, sum1, 2);
        l0 = l0 * al0 + sum0;
        l1 = l1 * al1 + sum1;
        m0 = mn0; m1 = mn1;
    }

    // ---- epilogue: fp16 hi/lo split attn output ----
    float inv0 = 1.f / l0, inv1 = 1.f / l1;
#pragma unroll
    for (int nf = 0; nf < 8; nf++) {
        int col = h * HDIM + nf * 8 + (lane & 3) * 2;
        size_t i0 = (size_t)(b * SEQ + r0g) * DMODEL + col;
        size_t i1 = (size_t)(b * SEQ + r1g) * DMODEL + col;
        store_split2h(Oh, Ol, i0, out[nf][0] * inv0, out[nf][1] * inv0);
        store_split2h(Oh, Ol, i1, out[nf][2] * inv1, out[nf][3] * inv1);
    }
}

// ---------------- launcher ---------------------------------------------------
extern "C" void kernel_launch(void* const* d_in, const int* in_sizes, int n_in,
                              void* d_out, int out_size)
{
    const float* x  = (const float*)d_in[0];
    const float* Wq = (const float*)d_in[2];
    const float* Wk = (const float*)d_in[3];
    const float* Wv = (const float*)d_in[4];
    const float* Wo = (const float*)d_in[5];
    float* out = (float*)d_out;

    float *kfb, *vfb;
    cudaGetSymbolAddress((void**)&kfb, g_kfb);
    cudaGetSymbolAddress((void**)&vfb, g_vfb);

    __half *xh, *xl, *wq, *wk, *wv, *wo, *qhf, *khf, *vhf;
    cudaGetSymbolAddress((void**)&xh, g_xh);
    cudaGetSymbolAddress((void**)&xl, g_xl);
    cudaGetSymbolAddress((void**)&wq, g_wq);
    cudaGetSymbolAddress((void**)&wk, g_wk);
    cudaGetSymbolAddress((void**)&wv, g_wv);
    cudaGetSymbolAddress((void**)&wo, g_wo);
    cudaGetSymbolAddress((void**)&qhf, g_qhf);
    cudaGetSymbolAddress((void**)&khf, g_khf);
    cudaGetSymbolAddress((void**)&vhf, g_vhf);

    float* kdst;
    float* vdst;
    if (out_size >= OUTN + 2 * KVN) {
        kdst = out + OUTN;
        vdst = out + OUTN + KVN;
    } else {
        kdst = kfb;
        vdst = vfb;
    }

    cudaFuncSetAttribute(mma_gemm, cudaFuncAttributeMaxDynamicSharedMemorySize, GEMM_SMEM);
    cudaFuncSetAttribute(qkv_gemm, cudaFuncAttributeMaxDynamicSharedMemorySize, GEMM_SMEM);
    cudaFuncSetAttribute(flash_mma, cudaFuncAttributeMaxDynamicSharedMemorySize, FLASH_SMEM);

    RopeTab tab;
    for (int p = 0; p < 32; p++) {
        double invf = exp(-(double)p * (log(10000.0) / 32.0));
        float hi = (float)invf;
        tab.hi[p] = hi;
        tab.lo[p] = (float)(invf - (double)hi);
    }

    // conversions: x split fp16, weights single fp16
    xsplit_kernel<<<OUTN/4/256, 256>>>((const float4*)x, (__half2*)xh, (__half2*)xl, OUTN/4);
    WPtrs wp;
    wp.s[0] = (const float4*)Wq; wp.d[0] = (__half2*)wq;
    wp.s[1] = (const float4*)Wk; wp.d[1] = (__half2*)wk;
    wp.s[2] = (const float4*)Wv; wp.d[2] = (__half2*)wv;
    wp.s[3] = (const float4*)Wo; wp.d[3] = (__half2*)wo;
    dim3 wgrid(WN/4/256, 4);
    wconv<<<wgrid, 256>>>(wp, WN/4);

    // fused QKV projection + RoPE + fp16 stores (128x64 tiles, 2 CTA/SM)
    dim3 ggrid(DMODEL / 64, MROWS / 128, 3);   // (16, 32, 3) = 1536 CTAs
    qkv_gemm<<<ggrid, 256, GEMM_SMEM>>>(xh, xl, wq, wk, wv,
                                        qhf, khf, vhf,
                                        kdst, vdst, tab);

    // tensor-core flash attention (all fp16) -> fp16-split attn output
    dim3 fgrid(SEQ / 128, NHEADS, BATCH);      // (16, 16, 2)
    flash_mma<<<fgrid, 256, FLASH_SMEM>>>(qhf, khf, vhf, xh, xl);

    // output projection (128x64 tiles, 2 CTA/SM)
    dim3 ogrid(DMODEL / 64, MROWS / 128);      // (16, 32) = 512 CTAs
    mma_gemm<<<ogrid, 256, GEMM_SMEM>>>(xh, xl, wo, out);
}